// round 6
// baseline (speedup 1.0000x reference)
#include <cuda_runtime.h>
#include <cuda_bf16.h>
#include <cstdint>

// ============================================================================
// Head_13: fused causal single-head attention. B=1024 T=128 C=384 HS=64 fp32.
// mma.sync m16n8k16 bf16 (plain sm_103-safe PTX) with hi/lo split emulation.
// One CTA per batch element, 512 threads (16 warps, 8x2 warp grid).
// ============================================================================

#define T_DIM 128
#define H_DIM 64

// row strides (bytes) — padded, conflict-free for ldmatrix
#define XSTR 144   // 64 bf16 + 16B pad
#define WSTR 144
#define QSTR 144
#define VSTR 272   // 128 bf16 + 16B pad
#define PSTR 272
#define SSTRW 129  // floats per S row

// ---- smem offsets ----
// Region A (phase 1 X/W; later S fp32)
#define XH_OFF 0
#define XL_OFF 18432
#define WH_OFF 36864
#define WL_OFF 64512
#define S_OFF  0                 // 128*129*4 = 66048 <= 92160
// Region B (Q/K hi/lo; later P hi/lo)
#define QH_OFF 92160
#define QL_OFF 110592
#define KH_OFF 129024
#define KL_OFF 147456
#define PH_OFF 92160
#define PL_OFF 126976
// Region C (V^T hi/lo)
#define VTH_OFF 165888
#define VTL_OFF 183296
#define SMEM_TOTAL 200704

// Pre-split, padded weight images: 6 chunks x [192 rows x 144B]
__device__ __align__(16) unsigned char g_wh[6 * 27648];
__device__ __align__(16) unsigned char g_wl[6 * 27648];

// ---------------------------------------------------------------------------
__device__ __forceinline__ uint32_t smem_u32(const void* p) {
    uint32_t a;
    asm("{ .reg .u64 t; cvta.to.shared.u64 t, %1; cvt.u32.u64 %0, t; }"
        : "=r"(a) : "l"(p));
    return a;
}
__device__ __forceinline__ void split2(float v, unsigned short& h, unsigned short& l) {
    __nv_bfloat16 hb = __float2bfloat16(v);
    float r = v - __bfloat162float(hb);
    __nv_bfloat16 lb = __float2bfloat16(r);
    h = __bfloat16_as_ushort(hb);
    l = __bfloat16_as_ushort(lb);
}
__device__ __forceinline__ uint32_t pack2(unsigned short a, unsigned short b) {
    return (uint32_t)a | ((uint32_t)b << 16);
}
__device__ __forceinline__ void ldmx4(uint32_t* r, uint32_t addr) {
    asm volatile("ldmatrix.sync.aligned.m8n8.x4.shared.b16 {%0,%1,%2,%3}, [%4];"
                 : "=r"(r[0]), "=r"(r[1]), "=r"(r[2]), "=r"(r[3]) : "r"(addr));
}
__device__ __forceinline__ void ldmx2(uint32_t* r, uint32_t addr) {
    asm volatile("ldmatrix.sync.aligned.m8n8.x2.shared.b16 {%0,%1}, [%2];"
                 : "=r"(r[0]), "=r"(r[1]) : "r"(addr));
}
__device__ __forceinline__ void mma16816(float* d, const uint32_t* a, const uint32_t* b) {
    asm volatile(
        "mma.sync.aligned.m16n8k16.row.col.f32.bf16.bf16.f32 "
        "{%0,%1,%2,%3}, {%4,%5,%6,%7}, {%8,%9}, {%0,%1,%2,%3};"
        : "+f"(d[0]), "+f"(d[1]), "+f"(d[2]), "+f"(d[3])
        : "r"(a[0]), "r"(a[1]), "r"(a[2]), "r"(a[3]), "r"(b[0]), "r"(b[1]));
}

// ---------------------------------------------------------------------------
// Prep: stacked transposed weights Wt[192][384] (rows 0-63 Wq^T, 64-127 Wk^T,
// 128-191 Wv^T), hi/lo split, padded chunk images in gmem scratch.
// ---------------------------------------------------------------------------
__global__ void prep_kernel(const float* __restrict__ Wq,
                            const float* __restrict__ Wk,
                            const float* __restrict__ Wv) {
    int idx = blockIdx.x * 256 + threadIdx.x;
    if (idx >= 192 * 384) return;
    int n = idx / 384, c = idx % 384;
    float w;
    if (n < 64)       w = Wq[c * 64 + n];
    else if (n < 128) w = Wk[c * 64 + (n - 64)];
    else              w = Wv[c * 64 + (n - 128)];
    unsigned short h, l;
    split2(w, h, l);
    int chunk = c >> 6, j = c & 63;
    uint32_t off = (uint32_t)chunk * 27648u + (uint32_t)n * WSTR + j * 2;
    *(unsigned short*)(g_wh + off) = h;
    *(unsigned short*)(g_wl + off) = l;
}

// ---------------------------------------------------------------------------
__global__ void __launch_bounds__(512, 1)
attn_kernel(const float* __restrict__ x, float* __restrict__ out) {
    extern __shared__ __align__(16) char sm[];
    const uint32_t smb = smem_u32(sm);
    const int tid  = threadIdx.x;
    const int lane = tid & 31;
    const int w    = tid >> 5;
    const int wm   = w >> 1;      // 0..7 : 16-row block
    const int wn   = w & 1;       // 0..1 : column half
    const int b    = blockIdx.x;
    const int rbase = wm * 16 + (lane >> 2);

    // ================= phase 1: [Q|K|V] = x @ Wt^T ==================
    float acc[12][4];
#pragma unroll
    for (int j = 0; j < 12; j++)
#pragma unroll
        for (int k = 0; k < 4; k++) acc[j][k] = 0.f;

    const float* xb = x + (size_t)b * (T_DIM * 384);
    for (int chunk = 0; chunk < 6; chunk++) {
        if (chunk) __syncthreads();  // previous MMA reads done before refill
        // x chunk [128 x 64] fp32 -> hi/lo bf16
        const float4* xs = (const float4*)(xb + chunk * 64);
#pragma unroll
        for (int it = 0; it < 4; it++) {
            int i = tid + it * 512;
            int t = i >> 4, f4 = i & 15;
            float4 v = xs[t * 96 + f4];
            unsigned short h0, h1, h2, h3, l0, l1, l2, l3;
            split2(v.x, h0, l0); split2(v.y, h1, l1);
            split2(v.z, h2, l2); split2(v.w, h3, l3);
            uint32_t off = (uint32_t)t * XSTR + f4 * 8;
            *(uint2*)(sm + XH_OFF + off) = make_uint2(pack2(h0, h1), pack2(h2, h3));
            *(uint2*)(sm + XL_OFF + off) = make_uint2(pack2(l0, l1), pack2(l2, l3));
        }
        // W chunk: flat 16B copies of pre-split padded image
        const uint4* wsh = (const uint4*)(g_wh + chunk * 27648);
        const uint4* wsl = (const uint4*)(g_wl + chunk * 27648);
        uint4* wdh = (uint4*)(sm + WH_OFF);
        uint4* wdl = (uint4*)(sm + WL_OFF);
        for (int i = tid; i < 1728; i += 512) { wdh[i] = wsh[i]; wdl[i] = wsl[i]; }
        __syncthreads();

#pragma unroll
        for (int split = 0; split < 3; split++) {
            uint32_t xoff = (split == 2) ? XL_OFF : XH_OFF;
            uint32_t woff = (split == 1) ? WL_OFF : WH_OFF;
#pragma unroll
            for (int ks = 0; ks < 4; ks++) {
                uint32_t a[4];
                ldmx4(a, smb + xoff + (wm * 16 + (lane & 15)) * XSTR
                         + ks * 32 + (lane >> 4) * 16);
#pragma unroll
                for (int nt = 0; nt < 12; nt++) {
                    uint32_t bb[2];
                    ldmx2(bb, smb + woff + (wn * 96 + nt * 8 + (lane & 7)) * WSTR
                              + ks * 32 + ((lane >> 3) & 1) * 16);
                    mma16816(acc[nt], a, bb);
                }
            }
        }
    }
    __syncthreads();

    // write Q/K (K-major hi/lo) and V^T (hi/lo)
#pragma unroll
    for (int nt = 0; nt < 12; nt++) {
        int g = wn * 96 + nt * 8 + 2 * (lane & 3);
        int r = rbase;
        unsigned short h0, l0, h1, l1, h2, l2, h3, l3;
        split2(acc[nt][0], h0, l0); split2(acc[nt][1], h1, l1);
        split2(acc[nt][2], h2, l2); split2(acc[nt][3], h3, l3);
        if (g < 128) {
            uint32_t bh = (g < 64) ? QH_OFF : KH_OFF;
            uint32_t bl = (g < 64) ? QL_OFF : KL_OFF;
            int gc = g & 63;
            *(uint32_t*)(sm + bh + (uint32_t)r * QSTR + gc * 2)       = pack2(h0, h1);
            *(uint32_t*)(sm + bl + (uint32_t)r * QSTR + gc * 2)       = pack2(l0, l1);
            *(uint32_t*)(sm + bh + (uint32_t)(r + 8) * QSTR + gc * 2) = pack2(h2, h3);
            *(uint32_t*)(sm + bl + (uint32_t)(r + 8) * QSTR + gc * 2) = pack2(l2, l3);
        } else {
            int hc = g - 128;  // V^T row
            *(unsigned short*)(sm + VTH_OFF + (uint32_t)hc * VSTR + r * 2)             = h0;
            *(unsigned short*)(sm + VTL_OFF + (uint32_t)hc * VSTR + r * 2)             = l0;
            *(unsigned short*)(sm + VTH_OFF + (uint32_t)(hc + 1) * VSTR + r * 2)       = h1;
            *(unsigned short*)(sm + VTL_OFF + (uint32_t)(hc + 1) * VSTR + r * 2)       = l1;
            *(unsigned short*)(sm + VTH_OFF + (uint32_t)hc * VSTR + (r + 8) * 2)       = h2;
            *(unsigned short*)(sm + VTL_OFF + (uint32_t)hc * VSTR + (r + 8) * 2)       = l2;
            *(unsigned short*)(sm + VTH_OFF + (uint32_t)(hc + 1) * VSTR + (r + 8) * 2) = h3;
            *(unsigned short*)(sm + VTL_OFF + (uint32_t)(hc + 1) * VSTR + (r + 8) * 2) = l3;
        }
    }
    __syncthreads();

    // ================= S = Q K^T (causal tiles only) =================
    {
        float sacc[8][4];
#pragma unroll
        for (int j = 0; j < 8; j++)
#pragma unroll
            for (int k = 0; k < 4; k++) sacc[j][k] = 0.f;

        const int rowmax = wm * 16 + 15;
#pragma unroll
        for (int split = 0; split < 3; split++) {
            uint32_t qoff = (split == 2) ? QL_OFF : QH_OFF;
            uint32_t koff = (split == 1) ? KL_OFF : KH_OFF;
#pragma unroll
            for (int ks = 0; ks < 4; ks++) {
                uint32_t a[4];
                ldmx4(a, smb + qoff + (wm * 16 + (lane & 15)) * QSTR
                         + ks * 32 + (lane >> 4) * 16);
#pragma unroll
                for (int nt = 0; nt < 8; nt++) {
                    int ncol = wn * 64 + nt * 8;
                    if (ncol <= rowmax) {
                        uint32_t bb[2];
                        ldmx2(bb, smb + koff + (ncol + (lane & 7)) * QSTR
                                  + ks * 32 + ((lane >> 3) & 1) * 16);
                        mma16816(sacc[nt], a, bb);
                    }
                }
            }
        }
        // S fp32 -> smem (stride 129 floats)
        float* sbuf = (float*)(sm + S_OFF);
        int r = rbase;
#pragma unroll
        for (int nt = 0; nt < 8; nt++) {
            int c = wn * 64 + nt * 8 + 2 * (lane & 3);
            if (c <= rowmax + 7) {
                sbuf[r * SSTRW + c]           = sacc[nt][0];
                sbuf[r * SSTRW + c + 1]       = sacc[nt][1];
                sbuf[(r + 8) * SSTRW + c]     = sacc[nt][2];
                sbuf[(r + 8) * SSTRW + c + 1] = sacc[nt][3];
            }
        }
    }
    __syncthreads();

    // ============ causal softmax: 4 threads per row, shfl reduce ============
    {
        const int row = tid >> 2;          // 0..127
        const int q   = tid & 3;           // quarter
        const float* sr = (const float*)(sm + S_OFF) + row * SSTRW;
        const int lo = q * 32;
        const int jend = min(lo + 32, row + 1);
        float m = -1e30f;
        for (int j = lo; j < jend; j++) m = fmaxf(m, sr[j]);
        m = fmaxf(m, __shfl_xor_sync(0xFFFFFFFFu, m, 1));
        m = fmaxf(m, __shfl_xor_sync(0xFFFFFFFFu, m, 2));
        float sum = 0.f;
        for (int j = lo; j < jend; j++) sum += __expf((sr[j] - m) * 0.125f);
        sum += __shfl_xor_sync(0xFFFFFFFFu, sum, 1);
        sum += __shfl_xor_sync(0xFFFFFFFFu, sum, 2);
        const float inv = 1.f / sum;
        __syncthreads();  // S reads done before P overwrites region B? (P!=S region; but Q/K dead)
        for (int j = lo; j < lo + 32; j += 2) {
            float e0 = (j     <= row) ? __expf((sr[j] - m) * 0.125f) * inv : 0.f;
            float e1 = (j + 1 <= row) ? __expf((sr[j + 1] - m) * 0.125f) * inv : 0.f;
            unsigned short h0, l0, h1, l1;
            split2(e0, h0, l0); split2(e1, h1, l1);
            uint32_t off = (uint32_t)row * PSTR + j * 2;
            *(uint32_t*)(sm + PH_OFF + off) = pack2(h0, h1);
            *(uint32_t*)(sm + PL_OFF + off) = pack2(l0, l1);
        }
    }
    __syncthreads();

    // ================= O = P V^T (skip all-zero k-tiles) =================
    {
        float oacc[4][4];
#pragma unroll
        for (int j = 0; j < 4; j++)
#pragma unroll
            for (int k = 0; k < 4; k++) oacc[j][k] = 0.f;

#pragma unroll
        for (int split = 0; split < 3; split++) {
            uint32_t aoff = (split == 2) ? PL_OFF : PH_OFF;
            uint32_t boff = (split == 1) ? VTL_OFF : VTH_OFF;
#pragma unroll
            for (int ks = 0; ks < 8; ks++) {
                if (ks <= wm) {
                    uint32_t a[4];
                    ldmx4(a, smb + aoff + (wm * 16 + (lane & 15)) * PSTR
                             + ks * 32 + (lane >> 4) * 16);
#pragma unroll
                    for (int nt = 0; nt < 4; nt++) {
                        uint32_t bb[2];
                        ldmx2(bb, smb + boff + (wn * 32 + nt * 8 + (lane & 7)) * VSTR
                                  + ks * 32 + ((lane >> 3) & 1) * 16);
                        mma16816(oacc[nt], a, bb);
                    }
                }
            }
        }
        // epilogue: fragments -> gmem
        int r = rbase;
#pragma unroll
        for (int nt = 0; nt < 4; nt++) {
            int c = wn * 32 + nt * 8 + 2 * (lane & 3);
            size_t o = ((size_t)b * T_DIM + r) * H_DIM + c;
            *(float2*)(out + o)             = make_float2(oacc[nt][0], oacc[nt][1]);
            *(float2*)(out + o + 8 * H_DIM) = make_float2(oacc[nt][2], oacc[nt][3]);
        }
    }
}

// ---------------------------------------------------------------------------
extern "C" void kernel_launch(void* const* d_in, const int* in_sizes, int n_in,
                              void* d_out, int out_size) {
    const float* x  = (const float*)d_in[0];
    const float* Wq = (const float*)d_in[1];
    const float* Wk = (const float*)d_in[2];
    const float* Wv = (const float*)d_in[3];
    float* out = (float*)d_out;

    cudaFuncSetAttribute(attn_kernel,
                         cudaFuncAttributeMaxDynamicSharedMemorySize, SMEM_TOTAL);

    prep_kernel<<<(192 * 384 + 255) / 256, 256>>>(Wq, Wk, Wv);
    attn_kernel<<<1024, 512, SMEM_TOTAL>>>(x, out);
}

// round 7
// speedup vs baseline: 1.5060x; 1.5060x over previous
#include <cuda_runtime.h>
#include <cuda_bf16.h>
#include <cstdint>

// ============================================================================
// Head_13: fused causal single-head attention. B=1024 T=128 C=384 HS=64 fp32.
// mma.sync m16n8k16 bf16 (plain sm_103-safe PTX) with hi/lo split emulation.
// One CTA per batch element, 512 threads, 4x4 warp grid (M=32, N-split=4).
// ============================================================================

#define T_DIM 128
#define H_DIM 64

// row strides (bytes) — padded, conflict-free for ldmatrix
#define XSTR 144   // 64 bf16 + 16B pad
#define WSTR 144
#define QSTR 144
#define VSTR 272   // 128 bf16 + 16B pad
#define PSTR 272
#define SSTRW 129  // floats per S row

// ---- smem offsets ----
// Region A (phase 1 X/W; later S fp32)
#define XH_OFF 0
#define XL_OFF 18432
#define WH_OFF 36864
#define WL_OFF 64512
#define S_OFF  0                 // 128*129*4 = 66048 <= 92160
// Region B (Q/K hi/lo; later P hi/lo)
#define QH_OFF 92160
#define QL_OFF 110592
#define KH_OFF 129024
#define KL_OFF 147456
#define PH_OFF 92160
#define PL_OFF 126976
// Region C (V^T hi/lo)
#define VTH_OFF 165888
#define VTL_OFF 183296
#define SMEM_TOTAL 200704

// Pre-split, padded weight images: 6 chunks x [192 rows x 144B]
__device__ __align__(16) unsigned char g_wh[6 * 27648];
__device__ __align__(16) unsigned char g_wl[6 * 27648];

// ---------------------------------------------------------------------------
__device__ __forceinline__ uint32_t smem_u32(const void* p) {
    uint32_t a;
    asm("{ .reg .u64 t; cvta.to.shared.u64 t, %1; cvt.u32.u64 %0, t; }"
        : "=r"(a) : "l"(p));
    return a;
}
__device__ __forceinline__ void split2(float v, unsigned short& h, unsigned short& l) {
    __nv_bfloat16 hb = __float2bfloat16(v);
    float r = v - __bfloat162float(hb);
    __nv_bfloat16 lb = __float2bfloat16(r);
    h = __bfloat16_as_ushort(hb);
    l = __bfloat16_as_ushort(lb);
}
__device__ __forceinline__ uint32_t pack2(unsigned short a, unsigned short b) {
    return (uint32_t)a | ((uint32_t)b << 16);
}
__device__ __forceinline__ void ldmx4(uint32_t* r, uint32_t addr) {
    asm volatile("ldmatrix.sync.aligned.m8n8.x4.shared.b16 {%0,%1,%2,%3}, [%4];"
                 : "=r"(r[0]), "=r"(r[1]), "=r"(r[2]), "=r"(r[3]) : "r"(addr));
}
__device__ __forceinline__ void ldmx2(uint32_t* r, uint32_t addr) {
    asm volatile("ldmatrix.sync.aligned.m8n8.x2.shared.b16 {%0,%1}, [%2];"
                 : "=r"(r[0]), "=r"(r[1]) : "r"(addr));
}
__device__ __forceinline__ void mma16816(float* d, const uint32_t* a, const uint32_t* b) {
    asm volatile(
        "mma.sync.aligned.m16n8k16.row.col.f32.bf16.bf16.f32 "
        "{%0,%1,%2,%3}, {%4,%5,%6,%7}, {%8,%9}, {%0,%1,%2,%3};"
        : "+f"(d[0]), "+f"(d[1]), "+f"(d[2]), "+f"(d[3])
        : "r"(a[0]), "r"(a[1]), "r"(a[2]), "r"(a[3]), "r"(b[0]), "r"(b[1]));
}
__device__ __forceinline__ void cp16(uint32_t saddr, const void* g) {
    asm volatile("cp.async.cg.shared.global [%0], [%1], 16;"
                 :: "r"(saddr), "l"(g));
}
#define CP_COMMIT() asm volatile("cp.async.commit_group;" ::: "memory")
#define CP_WAIT0()  asm volatile("cp.async.wait_group 0;" ::: "memory")

// ---------------------------------------------------------------------------
// Prep: stacked transposed weights Wt[192][384] (rows 0-63 Wq^T, 64-127 Wk^T,
// 128-191 Wv^T), hi/lo split, padded chunk images in gmem scratch.
// ---------------------------------------------------------------------------
__global__ void prep_kernel(const float* __restrict__ Wq,
                            const float* __restrict__ Wk,
                            const float* __restrict__ Wv) {
    int idx = blockIdx.x * 256 + threadIdx.x;
    if (idx >= 192 * 384) return;
    int n = idx / 384, c = idx % 384;
    float w;
    if (n < 64)       w = Wq[c * 64 + n];
    else if (n < 128) w = Wk[c * 64 + (n - 64)];
    else              w = Wv[c * 64 + (n - 128)];
    unsigned short h, l;
    split2(w, h, l);
    int chunk = c >> 6, j = c & 63;
    uint32_t off = (uint32_t)chunk * 27648u + (uint32_t)n * WSTR + j * 2;
    *(unsigned short*)(g_wh + off) = h;
    *(unsigned short*)(g_wl + off) = l;
}

// ---------------------------------------------------------------------------
__global__ void __launch_bounds__(512, 1)
attn_kernel(const float* __restrict__ x, float* __restrict__ out) {
    extern __shared__ __align__(16) char sm[];
    const uint32_t smb = smem_u32(sm);
    const int tid  = threadIdx.x;
    const int lane = tid & 31;
    const int w    = tid >> 5;
    const int wm   = w >> 2;      // 0..3 : 32-row block
    const int wn   = w & 3;       // 0..3 : column quarter
    const int b    = blockIdx.x;

    // ================= phase 1: [Q|K|V] = x @ Wt^T ==================
    float acc[2][6][4];
#pragma unroll
    for (int i = 0; i < 2; i++)
#pragma unroll
        for (int j = 0; j < 6; j++)
#pragma unroll
            for (int k = 0; k < 4; k++) acc[i][j][k] = 0.f;

    const float* xb = x + (size_t)b * (T_DIM * 384);
    for (int chunk = 0; chunk < 6; chunk++) {
        if (chunk) __syncthreads();  // previous MMA reads done before refill
        // W chunk via cp.async (in flight during x conversion)
        {
            const char* gsh = (const char*)(g_wh + chunk * 27648);
            const char* gsl = (const char*)(g_wl + chunk * 27648);
            for (int i = tid; i < 1728; i += 512) {
                cp16(smb + WH_OFF + i * 16, gsh + i * 16);
                cp16(smb + WL_OFF + i * 16, gsl + i * 16);
            }
            CP_COMMIT();
        }
        // x chunk [128 x 64] fp32 -> hi/lo bf16
        const float4* xs = (const float4*)(xb + chunk * 64);
#pragma unroll
        for (int it = 0; it < 4; it++) {
            int i = tid + it * 512;
            int t = i >> 4, f4 = i & 15;
            float4 v = xs[t * 96 + f4];
            unsigned short h0, h1, h2, h3, l0, l1, l2, l3;
            split2(v.x, h0, l0); split2(v.y, h1, l1);
            split2(v.z, h2, l2); split2(v.w, h3, l3);
            uint32_t off = (uint32_t)t * XSTR + f4 * 8;
            *(uint2*)(sm + XH_OFF + off) = make_uint2(pack2(h0, h1), pack2(h2, h3));
            *(uint2*)(sm + XL_OFF + off) = make_uint2(pack2(l0, l1), pack2(l2, l3));
        }
        CP_WAIT0();
        __syncthreads();

#pragma unroll
        for (int split = 0; split < 3; split++) {
            uint32_t xoff = (split == 2) ? XL_OFF : XH_OFF;
            uint32_t woff = (split == 1) ? WL_OFF : WH_OFF;
#pragma unroll
            for (int ks = 0; ks < 4; ks++) {
                uint32_t a[2][4];
#pragma unroll
                for (int mt = 0; mt < 2; mt++)
                    ldmx4(a[mt], smb + xoff + (wm * 32 + mt * 16 + (lane & 15)) * XSTR
                                 + ks * 32 + (lane >> 4) * 16);
#pragma unroll
                for (int nt = 0; nt < 6; nt++) {
                    uint32_t bb[2];
                    ldmx2(bb, smb + woff + (wn * 48 + nt * 8 + (lane & 7)) * WSTR
                              + ks * 32 + ((lane >> 3) & 1) * 16);
                    mma16816(acc[0][nt], a[0], bb);
                    mma16816(acc[1][nt], a[1], bb);
                }
            }
        }
    }
    __syncthreads();

    // write Q/K (K-major hi/lo) and V^T (hi/lo)
    const int rb0 = wm * 32 + (lane >> 2);
#pragma unroll
    for (int mt = 0; mt < 2; mt++) {
        int r = rb0 + mt * 16;
#pragma unroll
        for (int nt = 0; nt < 6; nt++) {
            int g = wn * 48 + nt * 8 + 2 * (lane & 3);
            unsigned short h0, l0, h1, l1, h2, l2, h3, l3;
            split2(acc[mt][nt][0], h0, l0); split2(acc[mt][nt][1], h1, l1);
            split2(acc[mt][nt][2], h2, l2); split2(acc[mt][nt][3], h3, l3);
            if (g < 128) {
                uint32_t bh = (g < 64) ? QH_OFF : KH_OFF;
                uint32_t bl = (g < 64) ? QL_OFF : KL_OFF;
                int gc = g & 63;
                *(uint32_t*)(sm + bh + (uint32_t)r * QSTR + gc * 2)       = pack2(h0, h1);
                *(uint32_t*)(sm + bl + (uint32_t)r * QSTR + gc * 2)       = pack2(l0, l1);
                *(uint32_t*)(sm + bh + (uint32_t)(r + 8) * QSTR + gc * 2) = pack2(h2, h3);
                *(uint32_t*)(sm + bl + (uint32_t)(r + 8) * QSTR + gc * 2) = pack2(l2, l3);
            } else {
                int hc = g - 128;  // V^T row
                *(unsigned short*)(sm + VTH_OFF + (uint32_t)hc * VSTR + r * 2)             = h0;
                *(unsigned short*)(sm + VTL_OFF + (uint32_t)hc * VSTR + r * 2)             = l0;
                *(unsigned short*)(sm + VTH_OFF + (uint32_t)(hc + 1) * VSTR + r * 2)       = h1;
                *(unsigned short*)(sm + VTL_OFF + (uint32_t)(hc + 1) * VSTR + r * 2)       = l1;
                *(unsigned short*)(sm + VTH_OFF + (uint32_t)hc * VSTR + (r + 8) * 2)       = h2;
                *(unsigned short*)(sm + VTL_OFF + (uint32_t)hc * VSTR + (r + 8) * 2)       = l2;
                *(unsigned short*)(sm + VTH_OFF + (uint32_t)(hc + 1) * VSTR + (r + 8) * 2) = h3;
                *(unsigned short*)(sm + VTL_OFF + (uint32_t)(hc + 1) * VSTR + (r + 8) * 2) = l3;
            }
        }
    }
    __syncthreads();

    // ================= S = Q K^T (causal tiles only) =================
    {
        float sacc[2][4][4];
#pragma unroll
        for (int i = 0; i < 2; i++)
#pragma unroll
            for (int j = 0; j < 4; j++)
#pragma unroll
                for (int k = 0; k < 4; k++) sacc[i][j][k] = 0.f;

#pragma unroll
        for (int split = 0; split < 3; split++) {
            uint32_t qoff = (split == 2) ? QL_OFF : QH_OFF;
            uint32_t koff = (split == 1) ? KL_OFF : KH_OFF;
#pragma unroll
            for (int ks = 0; ks < 4; ks++) {
                uint32_t a[2][4];
#pragma unroll
                for (int mt = 0; mt < 2; mt++)
                    ldmx4(a[mt], smb + qoff + (wm * 32 + mt * 16 + (lane & 15)) * QSTR
                                 + ks * 32 + (lane >> 4) * 16);
#pragma unroll
                for (int nt = 0; nt < 4; nt++) {
                    int ncol = wn * 32 + nt * 8;
                    if (ncol <= wm * 32 + 31) {
                        uint32_t bb[2];
                        ldmx2(bb, smb + koff + (ncol + (lane & 7)) * QSTR
                                  + ks * 32 + ((lane >> 3) & 1) * 16);
                        if (ncol <= wm * 32 + 15) mma16816(sacc[0][nt], a[0], bb);
                        mma16816(sacc[1][nt], a[1], bb);
                    }
                }
            }
        }
        // S fp32 -> smem (stride 129 floats, conflict-free)
        float* sbuf = (float*)(sm + S_OFF);
#pragma unroll
        for (int mt = 0; mt < 2; mt++) {
            int r = rb0 + mt * 16;
#pragma unroll
            for (int nt = 0; nt < 4; nt++) {
                int c = wn * 32 + nt * 8 + 2 * (lane & 3);
                if (c <= wm * 32 + 31) {
                    sbuf[r * SSTRW + c]           = sacc[mt][nt][0];
                    sbuf[r * SSTRW + c + 1]       = sacc[mt][nt][1];
                    sbuf[(r + 8) * SSTRW + c]     = sacc[mt][nt][2];
                    sbuf[(r + 8) * SSTRW + c + 1] = sacc[mt][nt][3];
                }
            }
        }
    }
    __syncthreads();

    // ============ causal softmax: 4 threads per row, shfl reduce ============
    {
        const int row = tid >> 2;          // 0..127
        const int q   = tid & 3;           // quarter
        const float* sr = (const float*)(sm + S_OFF) + row * SSTRW;
        const int lo = q * 32;
        const int jend = min(lo + 32, row + 1);
        float m = -1e30f;
        for (int j = lo; j < jend; j++) m = fmaxf(m, sr[j]);
        m = fmaxf(m, __shfl_xor_sync(0xFFFFFFFFu, m, 1));
        m = fmaxf(m, __shfl_xor_sync(0xFFFFFFFFu, m, 2));
        float sum = 0.f;
        for (int j = lo; j < jend; j++) sum += __expf((sr[j] - m) * 0.125f);
        sum += __shfl_xor_sync(0xFFFFFFFFu, sum, 1);
        sum += __shfl_xor_sync(0xFFFFFFFFu, sum, 2);
        const float inv = 1.f / sum;
        for (int j = lo; j < lo + 32; j += 2) {
            float e0 = (j     <= row) ? __expf((sr[j] - m) * 0.125f) * inv : 0.f;
            float e1 = (j + 1 <= row) ? __expf((sr[j + 1] - m) * 0.125f) * inv : 0.f;
            unsigned short h0, l0, h1, l1;
            split2(e0, h0, l0); split2(e1, h1, l1);
            uint32_t off = (uint32_t)row * PSTR + j * 2;
            *(uint32_t*)(sm + PH_OFF + off) = pack2(h0, h1);
            *(uint32_t*)(sm + PL_OFF + off) = pack2(l0, l1);
        }
    }
    __syncthreads();

    // ================= O = P V^T (skip all-zero k-tiles) =================
    {
        float oacc[2][2][4];
#pragma unroll
        for (int i = 0; i < 2; i++)
#pragma unroll
            for (int j = 0; j < 2; j++)
#pragma unroll
                for (int k = 0; k < 4; k++) oacc[i][j][k] = 0.f;

#pragma unroll
        for (int split = 0; split < 3; split++) {
            uint32_t aoff = (split == 2) ? PL_OFF : PH_OFF;
            uint32_t boff = (split == 1) ? VTL_OFF : VTH_OFF;
#pragma unroll
            for (int ks = 0; ks < 8; ks++) {
                if (ks <= 2 * wm + 1) {
                    uint32_t a[2][4];
#pragma unroll
                    for (int mt = 0; mt < 2; mt++)
                        if (ks <= 2 * wm + mt)
                            ldmx4(a[mt], smb + aoff
                                  + (wm * 32 + mt * 16 + (lane & 15)) * PSTR
                                  + ks * 32 + (lane >> 4) * 16);
#pragma unroll
                    for (int nt = 0; nt < 2; nt++) {
                        uint32_t bb[2];
                        ldmx2(bb, smb + boff + (wn * 16 + nt * 8 + (lane & 7)) * VSTR
                                  + ks * 32 + ((lane >> 3) & 1) * 16);
                        if (ks <= 2 * wm) mma16816(oacc[0][nt], a[0], bb);
                        mma16816(oacc[1][nt], a[1], bb);
                    }
                }
            }
        }
        // epilogue: fragments -> gmem
#pragma unroll
        for (int mt = 0; mt < 2; mt++) {
            int r = rb0 + mt * 16;
#pragma unroll
            for (int nt = 0; nt < 2; nt++) {
                int c = wn * 16 + nt * 8 + 2 * (lane & 3);
                size_t o = ((size_t)b * T_DIM + r) * H_DIM + c;
                *(float2*)(out + o)             = make_float2(oacc[mt][nt][0], oacc[mt][nt][1]);
                *(float2*)(out + o + 8 * H_DIM) = make_float2(oacc[mt][nt][2], oacc[mt][nt][3]);
            }
        }
    }
}

// ---------------------------------------------------------------------------
extern "C" void kernel_launch(void* const* d_in, const int* in_sizes, int n_in,
                              void* d_out, int out_size) {
    const float* x  = (const float*)d_in[0];
    const float* Wq = (const float*)d_in[1];
    const float* Wk = (const float*)d_in[2];
    const float* Wv = (const float*)d_in[3];
    float* out = (float*)d_out;

    cudaFuncSetAttribute(attn_kernel,
                         cudaFuncAttributeMaxDynamicSharedMemorySize, SMEM_TOTAL);

    prep_kernel<<<(192 * 384 + 255) / 256, 256>>>(Wq, Wk, Wv);
    attn_kernel<<<1024, 512, SMEM_TOTAL>>>(x, out);
}

// round 8
// speedup vs baseline: 1.7412x; 1.1562x over previous
#include <cuda_runtime.h>
#include <cuda_bf16.h>
#include <cstdint>

// ============================================================================
// Head_13: fused causal single-head attention. B=1024 T=128 C=384 HS=64 fp32.
// mma.sync m16n8k16 bf16 with hi/lo split emulation (3 MMA combos per product)
// issued from register-held fragments (A/B loaded once per tile).
// One CTA per batch element, 512 threads, 4x4 warp grid.
// ============================================================================

#define T_DIM 128
#define H_DIM 64

// row strides (bytes) — padded, conflict-free for ldmatrix
#define XSTR 144   // 64 bf16 + 16B pad
#define WSTR 144
#define QSTR 144
#define VSTR 272   // 128 bf16 + 16B pad
#define PSTR 272
#define SSTRW 129  // floats per S row

// ---- smem offsets ----
// Region A (phase 1 X/W; later S fp32)
#define XH_OFF 0
#define XL_OFF 18432
#define WH_OFF 36864
#define WL_OFF 64512
#define S_OFF  0                 // 128*129*4 = 66048 <= 92160
// Region B (Q/K hi/lo; later P hi/lo)
#define QH_OFF 92160
#define QL_OFF 110592
#define KH_OFF 129024
#define KL_OFF 147456
#define PH_OFF 92160
#define PL_OFF 126976
// Region C (V^T hi/lo)
#define VTH_OFF 165888
#define VTL_OFF 183296
#define SMEM_TOTAL 200704

// Pre-split, padded weight images: 6 chunks x [192 rows x 144B]
__device__ __align__(16) unsigned char g_wh[6 * 27648];
__device__ __align__(16) unsigned char g_wl[6 * 27648];

// ---------------------------------------------------------------------------
__device__ __forceinline__ uint32_t smem_u32(const void* p) {
    uint32_t a;
    asm("{ .reg .u64 t; cvta.to.shared.u64 t, %1; cvt.u32.u64 %0, t; }"
        : "=r"(a) : "l"(p));
    return a;
}
__device__ __forceinline__ void split2(float v, unsigned short& h, unsigned short& l) {
    __nv_bfloat16 hb = __float2bfloat16(v);
    float r = v - __bfloat162float(hb);
    __nv_bfloat16 lb = __float2bfloat16(r);
    h = __bfloat16_as_ushort(hb);
    l = __bfloat16_as_ushort(lb);
}
__device__ __forceinline__ uint32_t pack2(unsigned short a, unsigned short b) {
    return (uint32_t)a | ((uint32_t)b << 16);
}
__device__ __forceinline__ void ldmx4(uint32_t* r, uint32_t addr) {
    asm volatile("ldmatrix.sync.aligned.m8n8.x4.shared.b16 {%0,%1,%2,%3}, [%4];"
                 : "=r"(r[0]), "=r"(r[1]), "=r"(r[2]), "=r"(r[3]) : "r"(addr));
}
__device__ __forceinline__ void mma16816(float* d, const uint32_t* a, const uint32_t* b) {
    asm volatile(
        "mma.sync.aligned.m16n8k16.row.col.f32.bf16.bf16.f32 "
        "{%0,%1,%2,%3}, {%4,%5,%6,%7}, {%8,%9}, {%0,%1,%2,%3};"
        : "+f"(d[0]), "+f"(d[1]), "+f"(d[2]), "+f"(d[3])
        : "r"(a[0]), "r"(a[1]), "r"(a[2]), "r"(a[3]), "r"(b[0]), "r"(b[1]));
}
// 3-MMA emulated fp32 product: acc += Ah*Bh + Ah*Bl + Al*Bh
__device__ __forceinline__ void mma3(float* d, const uint32_t* ah, const uint32_t* al,
                                     const uint32_t* bh, const uint32_t* bl) {
    mma16816(d, ah, bh);
    mma16816(d, ah, bl);
    mma16816(d, al, bh);
}
__device__ __forceinline__ void cp16(uint32_t saddr, const void* g) {
    asm volatile("cp.async.cg.shared.global [%0], [%1], 16;"
                 :: "r"(saddr), "l"(g));
}
#define CP_COMMIT() asm volatile("cp.async.commit_group;" ::: "memory")
#define CP_WAIT0()  asm volatile("cp.async.wait_group 0;" ::: "memory")

// B-operand pair address for ldmatrix.x4 (two adjacent 8-col groups, K-major):
// rows colbase..+15, 16B halves select k0-7 / k8-15.
__device__ __forceinline__ uint32_t baddr(uint32_t base, int colbase, int ks,
                                          int lane, int stride) {
    return base + (uint32_t)(colbase + (lane & 7) + ((lane >> 4) & 1) * 8) * stride
         + ks * 32 + ((lane >> 3) & 1) * 16;
}
// A-operand address for ldmatrix.x4 (m16 x k16, row-major)
__device__ __forceinline__ uint32_t aaddr(uint32_t base, int rowbase, int ks,
                                          int lane, int stride) {
    return base + (uint32_t)(rowbase + (lane & 15)) * stride
         + ks * 32 + (lane >> 4) * 16;
}

// ---------------------------------------------------------------------------
// Prep: stacked transposed weights Wt[192][384], hi/lo split, padded images.
// ---------------------------------------------------------------------------
__global__ void prep_kernel(const float* __restrict__ Wq,
                            const float* __restrict__ Wk,
                            const float* __restrict__ Wv) {
    int idx = blockIdx.x * 256 + threadIdx.x;
    if (idx >= 192 * 384) return;
    int n = idx / 384, c = idx % 384;
    float w;
    if (n < 64)       w = Wq[c * 64 + n];
    else if (n < 128) w = Wk[c * 64 + (n - 64)];
    else              w = Wv[c * 64 + (n - 128)];
    unsigned short h, l;
    split2(w, h, l);
    int chunk = c >> 6, j = c & 63;
    uint32_t off = (uint32_t)chunk * 27648u + (uint32_t)n * WSTR + j * 2;
    *(unsigned short*)(g_wh + off) = h;
    *(unsigned short*)(g_wl + off) = l;
}

// ---------------------------------------------------------------------------
__global__ void __launch_bounds__(512, 1)
attn_kernel(const float* __restrict__ x, float* __restrict__ out) {
    extern __shared__ __align__(16) char sm[];
    const uint32_t smb = smem_u32(sm);
    const int tid  = threadIdx.x;
    const int lane = tid & 31;
    const int w    = tid >> 5;
    const int wm   = w >> 2;      // 0..3 : 32-row block
    const int wn   = w & 3;       // 0..3 : column quarter
    const int b    = blockIdx.x;

    // ================= phase 1: [Q|K|V] = x @ Wt^T ==================
    float acc[2][6][4];
#pragma unroll
    for (int i = 0; i < 2; i++)
#pragma unroll
        for (int j = 0; j < 6; j++)
#pragma unroll
            for (int k = 0; k < 4; k++) acc[i][j][k] = 0.f;

    const float* xb = x + (size_t)b * (T_DIM * 384);
    for (int chunk = 0; chunk < 6; chunk++) {
        if (chunk) __syncthreads();  // previous MMA reads done before refill
        // W chunk via cp.async (in flight during x conversion)
        {
            const char* gsh = (const char*)(g_wh + chunk * 27648);
            const char* gsl = (const char*)(g_wl + chunk * 27648);
            for (int i = tid; i < 1728; i += 512) {
                cp16(smb + WH_OFF + i * 16, gsh + i * 16);
                cp16(smb + WL_OFF + i * 16, gsl + i * 16);
            }
            CP_COMMIT();
        }
        // x chunk [128 x 64] fp32 -> hi/lo bf16
        const float4* xs = (const float4*)(xb + chunk * 64);
#pragma unroll
        for (int it = 0; it < 4; it++) {
            int i = tid + it * 512;
            int t = i >> 4, f4 = i & 15;
            float4 v = xs[t * 96 + f4];
            unsigned short h0, h1, h2, h3, l0, l1, l2, l3;
            split2(v.x, h0, l0); split2(v.y, h1, l1);
            split2(v.z, h2, l2); split2(v.w, h3, l3);
            uint32_t off = (uint32_t)t * XSTR + f4 * 8;
            *(uint2*)(sm + XH_OFF + off) = make_uint2(pack2(h0, h1), pack2(h2, h3));
            *(uint2*)(sm + XL_OFF + off) = make_uint2(pack2(l0, l1), pack2(l2, l3));
        }
        CP_WAIT0();
        __syncthreads();

#pragma unroll
        for (int ks = 0; ks < 4; ks++) {
            uint32_t ah[2][4], al[2][4];
#pragma unroll
            for (int mt = 0; mt < 2; mt++) {
                ldmx4(ah[mt], aaddr(smb + XH_OFF, wm * 32 + mt * 16, ks, lane, XSTR));
                ldmx4(al[mt], aaddr(smb + XL_OFF, wm * 32 + mt * 16, ks, lane, XSTR));
            }
#pragma unroll
            for (int np = 0; np < 3; np++) {
                uint32_t bh[4], bl[4];
                ldmx4(bh, baddr(smb + WH_OFF, wn * 48 + np * 16, ks, lane, WSTR));
                ldmx4(bl, baddr(smb + WL_OFF, wn * 48 + np * 16, ks, lane, WSTR));
#pragma unroll
                for (int half = 0; half < 2; half++) {
                    int nt = np * 2 + half;
#pragma unroll
                    for (int mt = 0; mt < 2; mt++)
                        mma3(acc[mt][nt], ah[mt], al[mt], bh + half * 2, bl + half * 2);
                }
            }
        }
    }
    __syncthreads();

    // write Q (pre-scaled by 0.125) / K (K-major hi/lo) and V^T (hi/lo)
    const int rb0 = wm * 32 + (lane >> 2);
#pragma unroll
    for (int mt = 0; mt < 2; mt++) {
        int r = rb0 + mt * 16;
#pragma unroll
        for (int nt = 0; nt < 6; nt++) {
            int g = wn * 48 + nt * 8 + 2 * (lane & 3);
            float sc = (g < 64) ? 0.125f : 1.f;   // fold softmax scale into Q
            unsigned short h0, l0, h1, l1, h2, l2, h3, l3;
            split2(acc[mt][nt][0] * sc, h0, l0); split2(acc[mt][nt][1] * sc, h1, l1);
            split2(acc[mt][nt][2] * sc, h2, l2); split2(acc[mt][nt][3] * sc, h3, l3);
            if (g < 128) {
                uint32_t bh = (g < 64) ? QH_OFF : KH_OFF;
                uint32_t bl = (g < 64) ? QL_OFF : KL_OFF;
                int gc = g & 63;
                *(uint32_t*)(sm + bh + (uint32_t)r * QSTR + gc * 2)       = pack2(h0, h1);
                *(uint32_t*)(sm + bl + (uint32_t)r * QSTR + gc * 2)       = pack2(l0, l1);
                *(uint32_t*)(sm + bh + (uint32_t)(r + 8) * QSTR + gc * 2) = pack2(h2, h3);
                *(uint32_t*)(sm + bl + (uint32_t)(r + 8) * QSTR + gc * 2) = pack2(l2, l3);
            } else {
                int hc = g - 128;  // V^T row
                *(unsigned short*)(sm + VTH_OFF + (uint32_t)hc * VSTR + r * 2)             = h0;
                *(unsigned short*)(sm + VTL_OFF + (uint32_t)hc * VSTR + r * 2)             = l0;
                *(unsigned short*)(sm + VTH_OFF + (uint32_t)(hc + 1) * VSTR + r * 2)       = h1;
                *(unsigned short*)(sm + VTL_OFF + (uint32_t)(hc + 1) * VSTR + r * 2)       = l1;
                *(unsigned short*)(sm + VTH_OFF + (uint32_t)hc * VSTR + (r + 8) * 2)       = h2;
                *(unsigned short*)(sm + VTL_OFF + (uint32_t)hc * VSTR + (r + 8) * 2)       = l2;
                *(unsigned short*)(sm + VTH_OFF + (uint32_t)(hc + 1) * VSTR + (r + 8) * 2) = h3;
                *(unsigned short*)(sm + VTL_OFF + (uint32_t)(hc + 1) * VSTR + (r + 8) * 2) = l3;
            }
        }
    }
    __syncthreads();

    // ================= S = Q K^T (causal tiles only) =================
    {
        float sacc[2][4][4];
#pragma unroll
        for (int i = 0; i < 2; i++)
#pragma unroll
            for (int j = 0; j < 4; j++)
#pragma unroll
                for (int k = 0; k < 4; k++) sacc[i][j][k] = 0.f;

        const int rowmax = wm * 32 + 31;
#pragma unroll
        for (int ks = 0; ks < 4; ks++) {
            uint32_t qh[2][4], ql[2][4];
#pragma unroll
            for (int mt = 0; mt < 2; mt++) {
                ldmx4(qh[mt], aaddr(smb + QH_OFF, wm * 32 + mt * 16, ks, lane, QSTR));
                ldmx4(ql[mt], aaddr(smb + QL_OFF, wm * 32 + mt * 16, ks, lane, QSTR));
            }
#pragma unroll
            for (int np = 0; np < 2; np++) {
                int ncol0 = wn * 32 + np * 16;
                if (ncol0 <= rowmax) {
                    uint32_t kh[4], kl[4];
                    ldmx4(kh, baddr(smb + KH_OFF, ncol0, ks, lane, QSTR));
                    ldmx4(kl, baddr(smb + KL_OFF, ncol0, ks, lane, QSTR));
#pragma unroll
                    for (int half = 0; half < 2; half++) {
                        int ncol = ncol0 + half * 8;
                        int nt = np * 2 + half;
                        if (ncol <= rowmax) {
                            if (ncol <= wm * 32 + 15)
                                mma3(sacc[0][nt], qh[0], ql[0], kh + half * 2, kl + half * 2);
                            mma3(sacc[1][nt], qh[1], ql[1], kh + half * 2, kl + half * 2);
                        }
                    }
                }
            }
        }
        // S fp32 -> smem (stride 129 floats, conflict-free)
        float* sbuf = (float*)(sm + S_OFF);
#pragma unroll
        for (int mt = 0; mt < 2; mt++) {
            int r = rb0 + mt * 16;
#pragma unroll
            for (int nt = 0; nt < 4; nt++) {
                int c = wn * 32 + nt * 8 + 2 * (lane & 3);
                if (c <= rowmax) {
                    sbuf[r * SSTRW + c]           = sacc[mt][nt][0];
                    sbuf[r * SSTRW + c + 1]       = sacc[mt][nt][1];
                    sbuf[(r + 8) * SSTRW + c]     = sacc[mt][nt][2];
                    sbuf[(r + 8) * SSTRW + c + 1] = sacc[mt][nt][3];
                }
            }
        }
    }
    __syncthreads();

    // ============ causal softmax: 4 threads per row, shfl reduce ============
    {
        const int row = tid >> 2;          // 0..127
        const int q   = tid & 3;           // quarter
        const float* sr = (const float*)(sm + S_OFF) + row * SSTRW;
        const int lo = q * 32;
        float sv[32];
#pragma unroll
        for (int jj = 0; jj < 32; jj++)
            sv[jj] = (lo + jj <= row) ? sr[lo + jj] : -1e30f;
        float m = -1e30f;
#pragma unroll
        for (int jj = 0; jj < 32; jj++) m = fmaxf(m, sv[jj]);
        m = fmaxf(m, __shfl_xor_sync(0xFFFFFFFFu, m, 1));
        m = fmaxf(m, __shfl_xor_sync(0xFFFFFFFFu, m, 2));
        float sum = 0.f;
#pragma unroll
        for (int jj = 0; jj < 32; jj++) {
            float e = (lo + jj <= row) ? __expf(sv[jj] - m) : 0.f;
            sv[jj] = e;
            sum += e;
        }
        sum += __shfl_xor_sync(0xFFFFFFFFu, sum, 1);
        sum += __shfl_xor_sync(0xFFFFFFFFu, sum, 2);
        const float inv = 1.f / sum;
#pragma unroll
        for (int jj = 0; jj < 32; jj += 2) {
            unsigned short h0, l0, h1, l1;
            split2(sv[jj] * inv, h0, l0);
            split2(sv[jj + 1] * inv, h1, l1);
            uint32_t off = (uint32_t)row * PSTR + (lo + jj) * 2;
            *(uint32_t*)(sm + PH_OFF + off) = pack2(h0, h1);
            *(uint32_t*)(sm + PL_OFF + off) = pack2(l0, l1);
        }
    }
    __syncthreads();

    // ================= O = P V^T (skip all-zero k-tiles) =================
    {
        float oacc[2][2][4];
#pragma unroll
        for (int i = 0; i < 2; i++)
#pragma unroll
            for (int j = 0; j < 2; j++)
#pragma unroll
                for (int k = 0; k < 4; k++) oacc[i][j][k] = 0.f;

#pragma unroll
        for (int ks = 0; ks < 8; ks++) {
            if (ks <= 2 * wm + 1) {
                uint32_t ph[2][4], pl[2][4];
#pragma unroll
                for (int mt = 0; mt < 2; mt++)
                    if (ks <= 2 * wm + mt) {
                        ldmx4(ph[mt], aaddr(smb + PH_OFF, wm * 32 + mt * 16, ks, lane, PSTR));
                        ldmx4(pl[mt], aaddr(smb + PL_OFF, wm * 32 + mt * 16, ks, lane, PSTR));
                    }
                uint32_t vh[4], vl[4];
                ldmx4(vh, baddr(smb + VTH_OFF, wn * 16, ks, lane, VSTR));
                ldmx4(vl, baddr(smb + VTL_OFF, wn * 16, ks, lane, VSTR));
#pragma unroll
                for (int half = 0; half < 2; half++) {
                    int nt = half;
                    if (ks <= 2 * wm)
                        mma3(oacc[0][nt], ph[0], pl[0], vh + half * 2, vl + half * 2);
                    mma3(oacc[1][nt], ph[1], pl[1], vh + half * 2, vl + half * 2);
                }
            }
        }
        // epilogue: fragments -> gmem
#pragma unroll
        for (int mt = 0; mt < 2; mt++) {
            int r = rb0 + mt * 16;
#pragma unroll
            for (int nt = 0; nt < 2; nt++) {
                int c = wn * 16 + nt * 8 + 2 * (lane & 3);
                size_t o = ((size_t)b * T_DIM + r) * H_DIM + c;
                *(float2*)(out + o)             = make_float2(oacc[mt][nt][0], oacc[mt][nt][1]);
                *(float2*)(out + o + 8 * H_DIM) = make_float2(oacc[mt][nt][2], oacc[mt][nt][3]);
            }
        }
    }
}

// ---------------------------------------------------------------------------
extern "C" void kernel_launch(void* const* d_in, const int* in_sizes, int n_in,
                              void* d_out, int out_size) {
    const float* x  = (const float*)d_in[0];
    const float* Wq = (const float*)d_in[1];
    const float* Wk = (const float*)d_in[2];
    const float* Wv = (const float*)d_in[3];
    float* out = (float*)d_out;

    cudaFuncSetAttribute(attn_kernel,
                         cudaFuncAttributeMaxDynamicSharedMemorySize, SMEM_TOTAL);

    prep_kernel<<<(192 * 384 + 255) / 256, 256>>>(Wq, Wk, Wv);
    attn_kernel<<<1024, 512, SMEM_TOTAL>>>(x, out);
}

// round 9
// speedup vs baseline: 2.0087x; 1.1537x over previous
#include <cuda_runtime.h>
#include <cuda_bf16.h>
#include <cuda_fp16.h>
#include <cstdint>

// ============================================================================
// Head_13: fused causal single-head attention. B=1024 T=128 C=384 HS=64 fp32.
// mma.sync m16n8k16 fp16 (fp32 accum). Phase 1 (QKV): x split fp16 hi/lo,
// W single fp16 -> 2 MMAs per product (~1.4e-4). S/O phases: 3-MMA hi/lo
// emulation (~2^-22). One CTA per batch, 512 threads, 4x4 warp grid.
// W double-buffered via cp.async ping-pong.
// ============================================================================

#define T_DIM 128
#define H_DIM 64

// row strides (bytes) — padded, conflict-free for ldmatrix
#define XSTR 144   // 64 fp16 + 16B pad
#define WSTR 144
#define QSTR 144
#define VSTR 272   // 128 fp16 + 16B pad
#define PSTR 272
#define SSTRW 129  // floats per S row

// ---- smem offsets ----
// Region A (phase 1 X hi/lo + W double buffer; later S fp32)
#define XH_OFF 0
#define XL_OFF 18432
#define WB0_OFF 36864
#define WB1_OFF 64512
#define S_OFF  0                 // 128*129*4 = 66048 <= 92160
// Region B (Q/K hi/lo; later P hi/lo)
#define QH_OFF 92160
#define QL_OFF 110592
#define KH_OFF 129024
#define KL_OFF 147456
#define PH_OFF 92160
#define PL_OFF 126976
// Region C (V^T hi/lo)
#define VTH_OFF 165888
#define VTL_OFF 183296
#define SMEM_TOTAL 200704

// Pre-split fp16 weight image: 6 chunks x [192 rows x 144B]
__device__ __align__(16) unsigned char g_wh[6 * 27648];

// ---------------------------------------------------------------------------
__device__ __forceinline__ uint32_t smem_u32(const void* p) {
    uint32_t a;
    asm("{ .reg .u64 t; cvta.to.shared.u64 t, %1; cvt.u32.u64 %0, t; }"
        : "=r"(a) : "l"(p));
    return a;
}
// fp32 -> fp16 hi + fp16 lo (residual)
__device__ __forceinline__ void split2h(float v, unsigned short& h, unsigned short& l) {
    __half hb = __float2half_rn(v);
    float r = v - __half2float(hb);
    __half lb = __float2half_rn(r);
    h = __half_as_ushort(hb);
    l = __half_as_ushort(lb);
}
__device__ __forceinline__ uint32_t pack2(unsigned short a, unsigned short b) {
    return (uint32_t)a | ((uint32_t)b << 16);
}
__device__ __forceinline__ void ldmx4(uint32_t* r, uint32_t addr) {
    asm volatile("ldmatrix.sync.aligned.m8n8.x4.shared.b16 {%0,%1,%2,%3}, [%4];"
                 : "=r"(r[0]), "=r"(r[1]), "=r"(r[2]), "=r"(r[3]) : "r"(addr));
}
__device__ __forceinline__ void mma16816(float* d, const uint32_t* a, const uint32_t* b) {
    asm volatile(
        "mma.sync.aligned.m16n8k16.row.col.f32.f16.f16.f32 "
        "{%0,%1,%2,%3}, {%4,%5,%6,%7}, {%8,%9}, {%0,%1,%2,%3};"
        : "+f"(d[0]), "+f"(d[1]), "+f"(d[2]), "+f"(d[3])
        : "r"(a[0]), "r"(a[1]), "r"(a[2]), "r"(a[3]), "r"(b[0]), "r"(b[1]));
}
// 3-MMA emulated fp32 product: acc += Ah*Bh + Ah*Bl + Al*Bh
__device__ __forceinline__ void mma3(float* d, const uint32_t* ah, const uint32_t* al,
                                     const uint32_t* bh, const uint32_t* bl) {
    mma16816(d, ah, bh);
    mma16816(d, ah, bl);
    mma16816(d, al, bh);
}
__device__ __forceinline__ void cp16(uint32_t saddr, const void* g) {
    asm volatile("cp.async.cg.shared.global [%0], [%1], 16;"
                 :: "r"(saddr), "l"(g));
}
#define CP_COMMIT() asm volatile("cp.async.commit_group;" ::: "memory")
#define CP_WAIT0()  asm volatile("cp.async.wait_group 0;" ::: "memory")
#define CP_WAIT1()  asm volatile("cp.async.wait_group 1;" ::: "memory")

// B-operand pair address for ldmatrix.x4 (two adjacent 8-col groups, K-major)
__device__ __forceinline__ uint32_t baddr(uint32_t base, int colbase, int ks,
                                          int lane, int stride) {
    return base + (uint32_t)(colbase + (lane & 7) + ((lane >> 4) & 1) * 8) * stride
         + ks * 32 + ((lane >> 3) & 1) * 16;
}
// A-operand address for ldmatrix.x4 (m16 x k16, row-major)
__device__ __forceinline__ uint32_t aaddr(uint32_t base, int rowbase, int ks,
                                          int lane, int stride) {
    return base + (uint32_t)(rowbase + (lane & 15)) * stride
         + ks * 32 + (lane >> 4) * 16;
}

// ---------------------------------------------------------------------------
// Prep: stacked transposed weights Wt[192][384] -> fp16, padded chunk images.
// ---------------------------------------------------------------------------
__global__ void prep_kernel(const float* __restrict__ Wq,
                            const float* __restrict__ Wk,
                            const float* __restrict__ Wv) {
    int idx = blockIdx.x * 256 + threadIdx.x;
    if (idx >= 192 * 384) return;
    int n = idx / 384, c = idx % 384;
    float w;
    if (n < 64)       w = Wq[c * 64 + n];
    else if (n < 128) w = Wk[c * 64 + (n - 64)];
    else              w = Wv[c * 64 + (n - 128)];
    int chunk = c >> 6, j = c & 63;
    uint32_t off = (uint32_t)chunk * 27648u + (uint32_t)n * WSTR + j * 2;
    *(unsigned short*)(g_wh + off) = __half_as_ushort(__float2half_rn(w));
}

// ---------------------------------------------------------------------------
__global__ void __launch_bounds__(512, 1)
attn_kernel(const float* __restrict__ x, float* __restrict__ out) {
    extern __shared__ __align__(16) char sm[];
    const uint32_t smb = smem_u32(sm);
    const int tid  = threadIdx.x;
    const int lane = tid & 31;
    const int w    = tid >> 5;
    const int wm   = w >> 2;      // 0..3 : 32-row block
    const int wn   = w & 3;       // 0..3 : column quarter
    const int b    = blockIdx.x;

    // ================= phase 1: [Q|K|V] = x @ Wt^T ==================
    float acc[2][6][4];
#pragma unroll
    for (int i = 0; i < 2; i++)
#pragma unroll
        for (int j = 0; j < 6; j++)
#pragma unroll
            for (int k = 0; k < 4; k++) acc[i][j][k] = 0.f;

    const float* xb = x + (size_t)b * (T_DIM * 384);
    // preload W chunk 0 into buffer 0
    {
        const char* gs = (const char*)g_wh;
        for (int i = tid; i < 1728; i += 512)
            cp16(smb + WB0_OFF + i * 16, gs + i * 16);
        CP_COMMIT();
    }
    for (int chunk = 0; chunk < 6; chunk++) {
        if (chunk) __syncthreads();  // prev MMA reads (X + other W buf) done
        // prefetch next W chunk into the other buffer
        if (chunk < 5) {
            const char* gs = (const char*)(g_wh + (chunk + 1) * 27648);
            uint32_t dst = smb + (((chunk + 1) & 1) ? WB1_OFF : WB0_OFF);
            for (int i = tid; i < 1728; i += 512)
                cp16(dst + i * 16, gs + i * 16);
            CP_COMMIT();
        }
        // x chunk [128 x 64] fp32 -> hi/lo fp16
        const float4* xs = (const float4*)(xb + chunk * 64);
#pragma unroll
        for (int it = 0; it < 4; it++) {
            int i = tid + it * 512;
            int t = i >> 4, f4 = i & 15;
            float4 v = xs[t * 96 + f4];
            unsigned short h0, h1, h2, h3, l0, l1, l2, l3;
            split2h(v.x, h0, l0); split2h(v.y, h1, l1);
            split2h(v.z, h2, l2); split2h(v.w, h3, l3);
            uint32_t off = (uint32_t)t * XSTR + f4 * 8;
            *(uint2*)(sm + XH_OFF + off) = make_uint2(pack2(h0, h1), pack2(h2, h3));
            *(uint2*)(sm + XL_OFF + off) = make_uint2(pack2(l0, l1), pack2(l2, l3));
        }
        if (chunk < 5) { CP_WAIT1(); } else { CP_WAIT0(); }
        __syncthreads();

        const uint32_t wbase = smb + ((chunk & 1) ? WB1_OFF : WB0_OFF);
#pragma unroll
        for (int ks = 0; ks < 4; ks++) {
            uint32_t ah[2][4], al[2][4];
#pragma unroll
            for (int mt = 0; mt < 2; mt++) {
                ldmx4(ah[mt], aaddr(smb + XH_OFF, wm * 32 + mt * 16, ks, lane, XSTR));
                ldmx4(al[mt], aaddr(smb + XL_OFF, wm * 32 + mt * 16, ks, lane, XSTR));
            }
#pragma unroll
            for (int np = 0; np < 3; np++) {
                uint32_t bh[4];
                ldmx4(bh, baddr(wbase, wn * 48 + np * 16, ks, lane, WSTR));
#pragma unroll
                for (int half = 0; half < 2; half++) {
                    int nt = np * 2 + half;
#pragma unroll
                    for (int mt = 0; mt < 2; mt++) {
                        mma16816(acc[mt][nt], ah[mt], bh + half * 2);
                        mma16816(acc[mt][nt], al[mt], bh + half * 2);
                    }
                }
            }
        }
    }
    __syncthreads();

    // write Q (pre-scaled by 0.125) / K (K-major hi/lo fp16) and V^T (hi/lo)
    const int rb0 = wm * 32 + (lane >> 2);
#pragma unroll
    for (int mt = 0; mt < 2; mt++) {
        int r = rb0 + mt * 16;
#pragma unroll
        for (int nt = 0; nt < 6; nt++) {
            int g = wn * 48 + nt * 8 + 2 * (lane & 3);
            float sc = (g < 64) ? 0.125f : 1.f;   // fold softmax scale into Q
            unsigned short h0, l0, h1, l1, h2, l2, h3, l3;
            split2h(acc[mt][nt][0] * sc, h0, l0); split2h(acc[mt][nt][1] * sc, h1, l1);
            split2h(acc[mt][nt][2] * sc, h2, l2); split2h(acc[mt][nt][3] * sc, h3, l3);
            if (g < 128) {
                uint32_t bh = (g < 64) ? QH_OFF : KH_OFF;
                uint32_t bl = (g < 64) ? QL_OFF : KL_OFF;
                int gc = g & 63;
                *(uint32_t*)(sm + bh + (uint32_t)r * QSTR + gc * 2)       = pack2(h0, h1);
                *(uint32_t*)(sm + bl + (uint32_t)r * QSTR + gc * 2)       = pack2(l0, l1);
                *(uint32_t*)(sm + bh + (uint32_t)(r + 8) * QSTR + gc * 2) = pack2(h2, h3);
                *(uint32_t*)(sm + bl + (uint32_t)(r + 8) * QSTR + gc * 2) = pack2(l2, l3);
            } else {
                int hc = g - 128;  // V^T row
                *(unsigned short*)(sm + VTH_OFF + (uint32_t)hc * VSTR + r * 2)             = h0;
                *(unsigned short*)(sm + VTL_OFF + (uint32_t)hc * VSTR + r * 2)             = l0;
                *(unsigned short*)(sm + VTH_OFF + (uint32_t)(hc + 1) * VSTR + r * 2)       = h1;
                *(unsigned short*)(sm + VTL_OFF + (uint32_t)(hc + 1) * VSTR + r * 2)       = l1;
                *(unsigned short*)(sm + VTH_OFF + (uint32_t)hc * VSTR + (r + 8) * 2)       = h2;
                *(unsigned short*)(sm + VTL_OFF + (uint32_t)hc * VSTR + (r + 8) * 2)       = l2;
                *(unsigned short*)(sm + VTH_OFF + (uint32_t)(hc + 1) * VSTR + (r + 8) * 2) = h3;
                *(unsigned short*)(sm + VTL_OFF + (uint32_t)(hc + 1) * VSTR + (r + 8) * 2) = l3;
            }
        }
    }
    __syncthreads();

    // ================= S = Q K^T (causal tiles only, 3-MMA) =================
    {
        float sacc[2][4][4];
#pragma unroll
        for (int i = 0; i < 2; i++)
#pragma unroll
            for (int j = 0; j < 4; j++)
#pragma unroll
                for (int k = 0; k < 4; k++) sacc[i][j][k] = 0.f;

        const int rowmax = wm * 32 + 31;
#pragma unroll
        for (int ks = 0; ks < 4; ks++) {
            uint32_t qh[2][4], ql[2][4];
#pragma unroll
            for (int mt = 0; mt < 2; mt++) {
                ldmx4(qh[mt], aaddr(smb + QH_OFF, wm * 32 + mt * 16, ks, lane, QSTR));
                ldmx4(ql[mt], aaddr(smb + QL_OFF, wm * 32 + mt * 16, ks, lane, QSTR));
            }
#pragma unroll
            for (int np = 0; np < 2; np++) {
                int ncol0 = wn * 32 + np * 16;
                if (ncol0 <= rowmax) {
                    uint32_t kh[4], kl[4];
                    ldmx4(kh, baddr(smb + KH_OFF, ncol0, ks, lane, QSTR));
                    ldmx4(kl, baddr(smb + KL_OFF, ncol0, ks, lane, QSTR));
#pragma unroll
                    for (int half = 0; half < 2; half++) {
                        int ncol = ncol0 + half * 8;
                        int nt = np * 2 + half;
                        if (ncol <= rowmax) {
                            if (ncol <= wm * 32 + 15)
                                mma3(sacc[0][nt], qh[0], ql[0], kh + half * 2, kl + half * 2);
                            mma3(sacc[1][nt], qh[1], ql[1], kh + half * 2, kl + half * 2);
                        }
                    }
                }
            }
        }
        // S fp32 -> smem (stride 129 floats, conflict-free)
        float* sbuf = (float*)(sm + S_OFF);
#pragma unroll
        for (int mt = 0; mt < 2; mt++) {
            int r = rb0 + mt * 16;
#pragma unroll
            for (int nt = 0; nt < 4; nt++) {
                int c = wn * 32 + nt * 8 + 2 * (lane & 3);
                if (c <= rowmax) {
                    sbuf[r * SSTRW + c]           = sacc[mt][nt][0];
                    sbuf[r * SSTRW + c + 1]       = sacc[mt][nt][1];
                    sbuf[(r + 8) * SSTRW + c]     = sacc[mt][nt][2];
                    sbuf[(r + 8) * SSTRW + c + 1] = sacc[mt][nt][3];
                }
            }
        }
    }
    __syncthreads();

    // ============ causal softmax: 4 threads per row, shfl reduce ============
    {
        const int row = tid >> 2;          // 0..127
        const int q   = tid & 3;           // quarter
        const float* sr = (const float*)(sm + S_OFF) + row * SSTRW;
        const int lo = q * 32;
        float sv[32];
#pragma unroll
        for (int jj = 0; jj < 32; jj++)
            sv[jj] = (lo + jj <= row) ? sr[lo + jj] : -1e30f;
        float m = -1e30f;
#pragma unroll
        for (int jj = 0; jj < 32; jj++) m = fmaxf(m, sv[jj]);
        m = fmaxf(m, __shfl_xor_sync(0xFFFFFFFFu, m, 1));
        m = fmaxf(m, __shfl_xor_sync(0xFFFFFFFFu, m, 2));
        float sum = 0.f;
#pragma unroll
        for (int jj = 0; jj < 32; jj++) {
            float e = (lo + jj <= row) ? __expf(sv[jj] - m) : 0.f;
            sv[jj] = e;
            sum += e;
        }
        sum += __shfl_xor_sync(0xFFFFFFFFu, sum, 1);
        sum += __shfl_xor_sync(0xFFFFFFFFu, sum, 2);
        const float inv = 1.f / sum;
#pragma unroll
        for (int jj = 0; jj < 32; jj += 2) {
            unsigned short h0, l0, h1, l1;
            split2h(sv[jj] * inv, h0, l0);
            split2h(sv[jj + 1] * inv, h1, l1);
            uint32_t off = (uint32_t)row * PSTR + (lo + jj) * 2;
            *(uint32_t*)(sm + PH_OFF + off) = pack2(h0, h1);
            *(uint32_t*)(sm + PL_OFF + off) = pack2(l0, l1);
        }
    }
    __syncthreads();

    // ================= O = P V^T (skip all-zero k-tiles, 3-MMA) =============
    {
        float oacc[2][2][4];
#pragma unroll
        for (int i = 0; i < 2; i++)
#pragma unroll
            for (int j = 0; j < 2; j++)
#pragma unroll
                for (int k = 0; k < 4; k++) oacc[i][j][k] = 0.f;

#pragma unroll
        for (int ks = 0; ks < 8; ks++) {
            if (ks <= 2 * wm + 1) {
                uint32_t ph[2][4], pl[2][4];
#pragma unroll
                for (int mt = 0; mt < 2; mt++)
                    if (ks <= 2 * wm + mt) {
                        ldmx4(ph[mt], aaddr(smb + PH_OFF, wm * 32 + mt * 16, ks, lane, PSTR));
                        ldmx4(pl[mt], aaddr(smb + PL_OFF, wm * 32 + mt * 16, ks, lane, PSTR));
                    }
                uint32_t vh[4], vl[4];
                ldmx4(vh, baddr(smb + VTH_OFF, wn * 16, ks, lane, VSTR));
                ldmx4(vl, baddr(smb + VTL_OFF, wn * 16, ks, lane, VSTR));
#pragma unroll
                for (int half = 0; half < 2; half++) {
                    int nt = half;
                    if (ks <= 2 * wm)
                        mma3(oacc[0][nt], ph[0], pl[0], vh + half * 2, vl + half * 2);
                    mma3(oacc[1][nt], ph[1], pl[1], vh + half * 2, vl + half * 2);
                }
            }
        }
        // epilogue: fragments -> gmem
#pragma unroll
        for (int mt = 0; mt < 2; mt++) {
            int r = rb0 + mt * 16;
#pragma unroll
            for (int nt = 0; nt < 2; nt++) {
                int c = wn * 16 + nt * 8 + 2 * (lane & 3);
                size_t o = ((size_t)b * T_DIM + r) * H_DIM + c;
                *(float2*)(out + o)             = make_float2(oacc[mt][nt][0], oacc[mt][nt][1]);
                *(float2*)(out + o + 8 * H_DIM) = make_float2(oacc[mt][nt][2], oacc[mt][nt][3]);
            }
        }
    }
}

// ---------------------------------------------------------------------------
extern "C" void kernel_launch(void* const* d_in, const int* in_sizes, int n_in,
                              void* d_out, int out_size) {
    const float* x  = (const float*)d_in[0];
    const float* Wq = (const float*)d_in[1];
    const float* Wk = (const float*)d_in[2];
    const float* Wv = (const float*)d_in[3];
    float* out = (float*)d_out;

    cudaFuncSetAttribute(attn_kernel,
                         cudaFuncAttributeMaxDynamicSharedMemorySize, SMEM_TOTAL);

    prep_kernel<<<(192 * 384 + 255) / 256, 256>>>(Wq, Wk, Wv);
    attn_kernel<<<1024, 512, SMEM_TOTAL>>>(x, out);
}

// round 10
// speedup vs baseline: 2.5524x; 1.2707x over previous
#include <cuda_runtime.h>
#include <cuda_fp16.h>
#include <cstdint>

// ============================================================================
// Head_13: fused causal single-head attention. B=1024 T=128 C=384 HS=64 fp32.
// mma.sync m16n8k16 fp16/fp32-acc. Phase 1: x hi/lo fp16 x W fp16 (2 MMAs).
// S: Q hi/lo x K (2 MMAs). O: P x V (1 MMA). Softmax on register fragments
// (online merge via 4KB partial buffer) — no S smem round trip.
// One CTA per batch, 512 threads, 4x4 warp grid.
// ============================================================================

#define T_DIM 128
#define H_DIM 64

// row strides (bytes) — padded, conflict-free for ldmatrix
#define XSTR 144   // 64 fp16 + 16B pad
#define WSTR 144
#define QSTR 144
#define VSTR 272   // 128 fp16 + 16B pad
#define PSTR 272

// ---- smem offsets ----
#define XH_OFF  0
#define XL_OFF  18432
#define WB0_OFF 36864
#define WB1_OFF 64512     // region A end 92160
#define QH_OFF  92160
#define QL_OFF  110592
#define KH_OFF  129024    // end 147456
#define PH_OFF  92160     // overlays QH/QL after S-phase reads (34816 <= 36864)
#define VTH_OFF 147456    // 17408
#define PART_OFF 164864   // 128 rows x 4 wn x float2 = 4096
#define SMEM_TOTAL 168960

// Pre-split fp16 weight image: 6 chunks x [192 rows x 144B]
__device__ __align__(16) unsigned char g_wh[6 * 27648];

// ---------------------------------------------------------------------------
__device__ __forceinline__ uint32_t smem_u32(const void* p) {
    uint32_t a;
    asm("{ .reg .u64 t; cvta.to.shared.u64 t, %1; cvt.u32.u64 %0, t; }"
        : "=r"(a) : "l"(p));
    return a;
}
// fp32 -> fp16 hi + fp16 lo (residual)
__device__ __forceinline__ void split2h(float v, unsigned short& h, unsigned short& l) {
    __half hb = __float2half_rn(v);
    float r = v - __half2float(hb);
    __half lb = __float2half_rn(r);
    h = __half_as_ushort(hb);
    l = __half_as_ushort(lb);
}
__device__ __forceinline__ unsigned short h16(float v) {
    return __half_as_ushort(__float2half_rn(v));
}
__device__ __forceinline__ uint32_t pack2(unsigned short a, unsigned short b) {
    return (uint32_t)a | ((uint32_t)b << 16);
}
__device__ __forceinline__ void ldmx4(uint32_t* r, uint32_t addr) {
    asm volatile("ldmatrix.sync.aligned.m8n8.x4.shared.b16 {%0,%1,%2,%3}, [%4];"
                 : "=r"(r[0]), "=r"(r[1]), "=r"(r[2]), "=r"(r[3]) : "r"(addr));
}
__device__ __forceinline__ void mma16816(float* d, const uint32_t* a, const uint32_t* b) {
    asm volatile(
        "mma.sync.aligned.m16n8k16.row.col.f32.f16.f16.f32 "
        "{%0,%1,%2,%3}, {%4,%5,%6,%7}, {%8,%9}, {%0,%1,%2,%3};"
        : "+f"(d[0]), "+f"(d[1]), "+f"(d[2]), "+f"(d[3])
        : "r"(a[0]), "r"(a[1]), "r"(a[2]), "r"(a[3]), "r"(b[0]), "r"(b[1]));
}
__device__ __forceinline__ void cp16(uint32_t saddr, const void* g) {
    asm volatile("cp.async.cg.shared.global [%0], [%1], 16;"
                 :: "r"(saddr), "l"(g));
}
#define CP_COMMIT() asm volatile("cp.async.commit_group;" ::: "memory")
#define CP_WAIT0()  asm volatile("cp.async.wait_group 0;" ::: "memory")
#define CP_WAIT1()  asm volatile("cp.async.wait_group 1;" ::: "memory")

// B-operand pair address for ldmatrix.x4 (two adjacent 8-col groups, K-major)
__device__ __forceinline__ uint32_t baddr(uint32_t base, int colbase, int ks,
                                          int lane, int stride) {
    return base + (uint32_t)(colbase + (lane & 7) + ((lane >> 4) & 1) * 8) * stride
         + ks * 32 + ((lane >> 3) & 1) * 16;
}
// A-operand address for ldmatrix.x4 (m16 x k16, row-major)
__device__ __forceinline__ uint32_t aaddr(uint32_t base, int rowbase, int ks,
                                          int lane, int stride) {
    return base + (uint32_t)(rowbase + (lane & 15)) * stride
         + ks * 32 + (lane >> 4) * 16;
}

// ---------------------------------------------------------------------------
// Prep: stacked transposed weights Wt[192][384] -> fp16, padded chunk images.
// ---------------------------------------------------------------------------
__global__ void prep_kernel(const float* __restrict__ Wq,
                            const float* __restrict__ Wk,
                            const float* __restrict__ Wv) {
    int idx = blockIdx.x * 256 + threadIdx.x;
    if (idx >= 192 * 384) return;
    int n = idx / 384, c = idx % 384;
    float w;
    if (n < 64)       w = Wq[c * 64 + n];
    else if (n < 128) w = Wk[c * 64 + (n - 64)];
    else              w = Wv[c * 64 + (n - 128)];
    int chunk = c >> 6, j = c & 63;
    uint32_t off = (uint32_t)chunk * 27648u + (uint32_t)n * WSTR + j * 2;
    *(unsigned short*)(g_wh + off) = h16(w);
}

// ---------------------------------------------------------------------------
__global__ void __launch_bounds__(512, 1)
attn_kernel(const float* __restrict__ x, float* __restrict__ out) {
    extern __shared__ __align__(16) char sm[];
    const uint32_t smb = smem_u32(sm);
    const int tid  = threadIdx.x;
    const int lane = tid & 31;
    const int w    = tid >> 5;
    const int wm   = w >> 2;      // 0..3 : 32-row block
    const int wn   = w & 3;       // 0..3 : column quarter
    const int b    = blockIdx.x;

    // ================= phase 1: [Q|K|V] = x @ Wt^T ==================
    float acc[2][6][4];
#pragma unroll
    for (int i = 0; i < 2; i++)
#pragma unroll
        for (int j = 0; j < 6; j++)
#pragma unroll
            for (int k = 0; k < 4; k++) acc[i][j][k] = 0.f;

    const float* xb = x + (size_t)b * (T_DIM * 384);
    // preload W chunk 0 + x chunk 0 regs
    {
        const char* gs = (const char*)g_wh;
        for (int i = tid; i < 1728; i += 512)
            cp16(smb + WB0_OFF + i * 16, gs + i * 16);
        CP_COMMIT();
    }
    float4 xv[4];
#pragma unroll
    for (int it = 0; it < 4; it++) {
        int i = tid + it * 512;
        xv[it] = ((const float4*)xb)[(i >> 4) * 96 + (i & 15)];
    }

    for (int chunk = 0; chunk < 6; chunk++) {
        if (chunk) __syncthreads();  // prev MMA reads done before refill
        // x chunk regs -> hi/lo fp16 smem
#pragma unroll
        for (int it = 0; it < 4; it++) {
            int i = tid + it * 512;
            int t = i >> 4, f4 = i & 15;
            float4 v = xv[it];
            unsigned short h0, h1, h2, h3, l0, l1, l2, l3;
            split2h(v.x, h0, l0); split2h(v.y, h1, l1);
            split2h(v.z, h2, l2); split2h(v.w, h3, l3);
            uint32_t off = (uint32_t)t * XSTR + f4 * 8;
            *(uint2*)(sm + XH_OFF + off) = make_uint2(pack2(h0, h1), pack2(h2, h3));
            *(uint2*)(sm + XL_OFF + off) = make_uint2(pack2(l0, l1), pack2(l2, l3));
        }
        // prefetch next W chunk into the other buffer
        if (chunk < 5) {
            const char* gs = (const char*)(g_wh + (chunk + 1) * 27648);
            uint32_t dst = smb + (((chunk + 1) & 1) ? WB1_OFF : WB0_OFF);
            for (int i = tid; i < 1728; i += 512)
                cp16(dst + i * 16, gs + i * 16);
            CP_COMMIT();
            CP_WAIT1();
        } else {
            CP_WAIT0();
        }
        __syncthreads();
        // prefetch next x chunk into regs (LDG latency hidden by MMAs)
        if (chunk < 5) {
            const float4* xs = (const float4*)(xb + (chunk + 1) * 64);
#pragma unroll
            for (int it = 0; it < 4; it++) {
                int i = tid + it * 512;
                xv[it] = xs[(i >> 4) * 96 + (i & 15)];
            }
        }

        const uint32_t wbase = smb + ((chunk & 1) ? WB1_OFF : WB0_OFF);
#pragma unroll
        for (int ks = 0; ks < 4; ks++) {
            uint32_t ah[2][4], al[2][4];
#pragma unroll
            for (int mt = 0; mt < 2; mt++) {
                ldmx4(ah[mt], aaddr(smb + XH_OFF, wm * 32 + mt * 16, ks, lane, XSTR));
                ldmx4(al[mt], aaddr(smb + XL_OFF, wm * 32 + mt * 16, ks, lane, XSTR));
            }
#pragma unroll
            for (int np = 0; np < 3; np++) {
                uint32_t bh[4];
                ldmx4(bh, baddr(wbase, wn * 48 + np * 16, ks, lane, WSTR));
#pragma unroll
                for (int half = 0; half < 2; half++) {
                    int nt = np * 2 + half;
#pragma unroll
                    for (int mt = 0; mt < 2; mt++) {
                        mma16816(acc[mt][nt], ah[mt], bh + half * 2);
                        mma16816(acc[mt][nt], al[mt], bh + half * 2);
                    }
                }
            }
        }
    }
    __syncthreads();

    // write Q (x0.125, hi/lo) / K (single fp16) / V^T (single fp16)
    const int rb0 = wm * 32 + (lane >> 2);
#pragma unroll
    for (int mt = 0; mt < 2; mt++) {
        int r = rb0 + mt * 16;
#pragma unroll
        for (int nt = 0; nt < 6; nt++) {
            int g = wn * 48 + nt * 8 + 2 * (lane & 3);
            if (g < 64) {             // Q hi/lo, pre-scaled
                unsigned short h0, l0, h1, l1, h2, l2, h3, l3;
                split2h(acc[mt][nt][0] * 0.125f, h0, l0);
                split2h(acc[mt][nt][1] * 0.125f, h1, l1);
                split2h(acc[mt][nt][2] * 0.125f, h2, l2);
                split2h(acc[mt][nt][3] * 0.125f, h3, l3);
                *(uint32_t*)(sm + QH_OFF + (uint32_t)r * QSTR + g * 2)       = pack2(h0, h1);
                *(uint32_t*)(sm + QL_OFF + (uint32_t)r * QSTR + g * 2)       = pack2(l0, l1);
                *(uint32_t*)(sm + QH_OFF + (uint32_t)(r + 8) * QSTR + g * 2) = pack2(h2, h3);
                *(uint32_t*)(sm + QL_OFF + (uint32_t)(r + 8) * QSTR + g * 2) = pack2(l2, l3);
            } else if (g < 128) {     // K single fp16
                int gc = g - 64;
                *(uint32_t*)(sm + KH_OFF + (uint32_t)r * QSTR + gc * 2) =
                    pack2(h16(acc[mt][nt][0]), h16(acc[mt][nt][1]));
                *(uint32_t*)(sm + KH_OFF + (uint32_t)(r + 8) * QSTR + gc * 2) =
                    pack2(h16(acc[mt][nt][2]), h16(acc[mt][nt][3]));
            } else {                  // V^T single fp16
                int hc = g - 128;
                *(unsigned short*)(sm + VTH_OFF + (uint32_t)hc * VSTR + r * 2)             = h16(acc[mt][nt][0]);
                *(unsigned short*)(sm + VTH_OFF + (uint32_t)(hc + 1) * VSTR + r * 2)       = h16(acc[mt][nt][1]);
                *(unsigned short*)(sm + VTH_OFF + (uint32_t)hc * VSTR + (r + 8) * 2)       = h16(acc[mt][nt][2]);
                *(unsigned short*)(sm + VTH_OFF + (uint32_t)(hc + 1) * VSTR + (r + 8) * 2) = h16(acc[mt][nt][3]);
            }
        }
    }
    __syncthreads();

    // ================= S = Q K^T (causal tiles, 2-MMA) + fragment softmax ====
    float sacc[2][4][4];
#pragma unroll
    for (int i = 0; i < 2; i++)
#pragma unroll
        for (int j = 0; j < 4; j++)
#pragma unroll
            for (int k = 0; k < 4; k++) sacc[i][j][k] = 0.f;

    {
        const int rowmax = wm * 32 + 31;
#pragma unroll
        for (int ks = 0; ks < 4; ks++) {
            uint32_t qh[2][4], ql[2][4];
#pragma unroll
            for (int mt = 0; mt < 2; mt++) {
                ldmx4(qh[mt], aaddr(smb + QH_OFF, wm * 32 + mt * 16, ks, lane, QSTR));
                ldmx4(ql[mt], aaddr(smb + QL_OFF, wm * 32 + mt * 16, ks, lane, QSTR));
            }
#pragma unroll
            for (int np = 0; np < 2; np++) {
                int ncol0 = wn * 32 + np * 16;
                if (ncol0 <= rowmax) {
                    uint32_t kh[4];
                    ldmx4(kh, baddr(smb + KH_OFF, ncol0, ks, lane, QSTR));
#pragma unroll
                    for (int half = 0; half < 2; half++) {
                        int ncol = ncol0 + half * 8;
                        int nt = np * 2 + half;
                        if (ncol <= rowmax) {
                            if (ncol <= wm * 32 + 15) {
                                mma16816(sacc[0][nt], qh[0], kh + half * 2);
                                mma16816(sacc[0][nt], ql[0], kh + half * 2);
                            }
                            mma16816(sacc[1][nt], qh[1], kh + half * 2);
                            mma16816(sacc[1][nt], ql[1], kh + half * 2);
                        }
                    }
                }
            }
        }
    }

    // ---- softmax on fragments: mask, local (max,sum), merge via smem ----
    float mloc[4], sloc[4];
#pragma unroll
    for (int ri = 0; ri < 4; ri++) {
        int mt = ri >> 1, hb = ri & 1;
        int r = rb0 + mt * 16 + hb * 8;
        float m = -1e30f;
#pragma unroll
        for (int nt = 0; nt < 4; nt++) {
            int c = wn * 32 + nt * 8 + 2 * (lane & 3);
#pragma unroll
            for (int vv = 0; vv < 2; vv++) {
                float val = (c + vv <= r) ? sacc[mt][nt][hb * 2 + vv] : -1e30f;
                sacc[mt][nt][hb * 2 + vv] = val;
                m = fmaxf(m, val);
            }
        }
        m = fmaxf(m, __shfl_xor_sync(0xFFFFFFFFu, m, 1));
        m = fmaxf(m, __shfl_xor_sync(0xFFFFFFFFu, m, 2));
        float s = 0.f;
#pragma unroll
        for (int nt = 0; nt < 4; nt++)
#pragma unroll
            for (int vv = 0; vv < 2; vv++) {
                float e = __expf(sacc[mt][nt][hb * 2 + vv] - m);
                sacc[mt][nt][hb * 2 + vv] = e;
                s += e;
            }
        s += __shfl_xor_sync(0xFFFFFFFFu, s, 1);
        s += __shfl_xor_sync(0xFFFFFFFFu, s, 2);
        mloc[ri] = m;
        sloc[ri] = s;
        if ((lane & 3) == 0)
            *(float2*)(sm + PART_OFF + ((uint32_t)r * 4 + wn) * 8) = make_float2(m, s);
    }
    __syncthreads();

    // merge partials, write P (single fp16) — overlays dead Q region
#pragma unroll
    for (int ri = 0; ri < 4; ri++) {
        int mt = ri >> 1, hb = ri & 1;
        int r = rb0 + mt * 16 + hb * 8;
        const float2* pp = (const float2*)(sm + PART_OFF + (uint32_t)r * 32);
        float2 p0 = pp[0], p1 = pp[1], p2 = pp[2], p3 = pp[3];
        float mg = fmaxf(fmaxf(p0.x, p1.x), fmaxf(p2.x, p3.x));
        float sg = p0.y * __expf(p0.x - mg) + p1.y * __expf(p1.x - mg)
                 + p2.y * __expf(p2.x - mg) + p3.y * __expf(p3.x - mg);
        float fac = __expf(mloc[ri] - mg) / sg;
#pragma unroll
        for (int nt = 0; nt < 4; nt++) {
            int c = wn * 32 + nt * 8 + 2 * (lane & 3);
            *(uint32_t*)(sm + PH_OFF + (uint32_t)r * PSTR + c * 2) =
                pack2(h16(sacc[mt][nt][hb * 2] * fac),
                      h16(sacc[mt][nt][hb * 2 + 1] * fac));
        }
    }
    __syncthreads();

    // ================= O = P V^T (causal k-tiles, 1-MMA) =================
    {
        float oacc[2][2][4];
#pragma unroll
        for (int i = 0; i < 2; i++)
#pragma unroll
            for (int j = 0; j < 2; j++)
#pragma unroll
                for (int k = 0; k < 4; k++) oacc[i][j][k] = 0.f;

#pragma unroll
        for (int ks = 0; ks < 8; ks++) {
            if (ks <= 2 * wm + 1) {
                uint32_t ph[2][4];
#pragma unroll
                for (int mt = 0; mt < 2; mt++)
                    if (ks <= 2 * wm + mt)
                        ldmx4(ph[mt], aaddr(smb + PH_OFF, wm * 32 + mt * 16, ks, lane, PSTR));
                uint32_t vh[4];
                ldmx4(vh, baddr(smb + VTH_OFF, wn * 16, ks, lane, VSTR));
#pragma unroll
                for (int half = 0; half < 2; half++) {
                    if (ks <= 2 * wm)
                        mma16816(oacc[0][half], ph[0], vh + half * 2);
                    mma16816(oacc[1][half], ph[1], vh + half * 2);
                }
            }
        }
        // epilogue: fragments -> gmem
#pragma unroll
        for (int mt = 0; mt < 2; mt++) {
            int r = rb0 + mt * 16;
#pragma unroll
            for (int nt = 0; nt < 2; nt++) {
                int c = wn * 16 + nt * 8 + 2 * (lane & 3);
                size_t o = ((size_t)b * T_DIM + r) * H_DIM + c;
                *(float2*)(out + o)             = make_float2(oacc[mt][nt][0], oacc[mt][nt][1]);
                *(float2*)(out + o + 8 * H_DIM) = make_float2(oacc[mt][nt][2], oacc[mt][nt][3]);
            }
        }
    }
}

// ---------------------------------------------------------------------------
extern "C" void kernel_launch(void* const* d_in, const int* in_sizes, int n_in,
                              void* d_out, int out_size) {
    const float* x  = (const float*)d_in[0];
    const float* Wq = (const float*)d_in[1];
    const float* Wk = (const float*)d_in[2];
    const float* Wv = (const float*)d_in[3];
    float* out = (float*)d_out;

    cudaFuncSetAttribute(attn_kernel,
                         cudaFuncAttributeMaxDynamicSharedMemorySize, SMEM_TOTAL);

    prep_kernel<<<(192 * 384 + 255) / 256, 256>>>(Wq, Wk, Wv);
    attn_kernel<<<1024, 512, SMEM_TOTAL>>>(x, out);
}

// round 11
// speedup vs baseline: 2.7109x; 1.0621x over previous
#include <cuda_runtime.h>
#include <cuda_fp16.h>
#include <cstdint>

// ============================================================================
// Head_13: fused causal single-head attention. B=1024 T=128 C=384 HS=64 fp32.
// mma.sync m16n8k16 fp16/fp32-acc. Phase 1: x hi/lo fp16 x W fp16 (2 MMAs).
// S: Q hi/lo x K (2 MMAs). O: P x V (1 MMA, ldmatrix.trans on row-major V).
// Causal-balanced warp mapping: warp wm owns row blocks {wm, 7-wm}.
// One CTA per batch, 512 threads, 4x4 warp grid.
// ============================================================================

#define T_DIM 128
#define H_DIM 64

// row strides (bytes) — padded, conflict-free for ldmatrix
#define XSTR 144   // 64 fp16 + 16B pad
#define WSTR 144
#define QSTR 144
#define PSTR 272   // 128 fp16 + 16B pad

// ---- smem offsets ----
#define XH_OFF  0
#define XL_OFF  18432
#define WB0_OFF 36864
#define WB1_OFF 64512     // region A end 92160
#define QH_OFF  92160
#define QL_OFF  110592
#define KH_OFF  129024    // end 147456
#define PH_OFF  92160     // overlays QH/QL after S-phase reads (34816 <= 36864)
#define V_OFF   147456    // V row-major [128][64], stride 144 -> 18432
#define PART_OFF 165888   // 128 rows x 4 wn x float2 = 4096
#define SMEM_TOTAL 169984

// Pre-split fp16 weight image: 6 chunks x [192 rows x 144B]
__device__ __align__(16) unsigned char g_wh[6 * 27648];

// ---------------------------------------------------------------------------
__device__ __forceinline__ uint32_t smem_u32(const void* p) {
    uint32_t a;
    asm("{ .reg .u64 t; cvta.to.shared.u64 t, %1; cvt.u32.u64 %0, t; }"
        : "=r"(a) : "l"(p));
    return a;
}
// fp32 -> fp16 hi + fp16 lo (residual)
__device__ __forceinline__ void split2h(float v, unsigned short& h, unsigned short& l) {
    __half hb = __float2half_rn(v);
    float r = v - __half2float(hb);
    __half lb = __float2half_rn(r);
    h = __half_as_ushort(hb);
    l = __half_as_ushort(lb);
}
__device__ __forceinline__ unsigned short h16(float v) {
    return __half_as_ushort(__float2half_rn(v));
}
__device__ __forceinline__ uint32_t pack2(unsigned short a, unsigned short b) {
    return (uint32_t)a | ((uint32_t)b << 16);
}
__device__ __forceinline__ void ldmx4(uint32_t* r, uint32_t addr) {
    asm volatile("ldmatrix.sync.aligned.m8n8.x4.shared.b16 {%0,%1,%2,%3}, [%4];"
                 : "=r"(r[0]), "=r"(r[1]), "=r"(r[2]), "=r"(r[3]) : "r"(addr));
}
__device__ __forceinline__ void ldmx4t(uint32_t* r, uint32_t addr) {
    asm volatile("ldmatrix.sync.aligned.m8n8.x4.trans.shared.b16 {%0,%1,%2,%3}, [%4];"
                 : "=r"(r[0]), "=r"(r[1]), "=r"(r[2]), "=r"(r[3]) : "r"(addr));
}
__device__ __forceinline__ void mma16816(float* d, const uint32_t* a, const uint32_t* b) {
    asm volatile(
        "mma.sync.aligned.m16n8k16.row.col.f32.f16.f16.f32 "
        "{%0,%1,%2,%3}, {%4,%5,%6,%7}, {%8,%9}, {%0,%1,%2,%3};"
        : "+f"(d[0]), "+f"(d[1]), "+f"(d[2]), "+f"(d[3])
        : "r"(a[0]), "r"(a[1]), "r"(a[2]), "r"(a[3]), "r"(b[0]), "r"(b[1]));
}
__device__ __forceinline__ void cp16(uint32_t saddr, const void* g) {
    asm volatile("cp.async.cg.shared.global [%0], [%1], 16;"
                 :: "r"(saddr), "l"(g));
}
#define CP_COMMIT() asm volatile("cp.async.commit_group;" ::: "memory")
#define CP_WAIT0()  asm volatile("cp.async.wait_group 0;" ::: "memory")
#define CP_WAIT1()  asm volatile("cp.async.wait_group 1;" ::: "memory")

// B-operand pair address for ldmatrix.x4 (two adjacent 8-col groups, K-major)
__device__ __forceinline__ uint32_t baddr(uint32_t base, int colbase, int ks,
                                          int lane, int stride) {
    return base + (uint32_t)(colbase + (lane & 7) + ((lane >> 4) & 1) * 8) * stride
         + ks * 32 + ((lane >> 3) & 1) * 16;
}
// A-operand address for ldmatrix.x4 (m16 x k16, row-major)
__device__ __forceinline__ uint32_t aaddr(uint32_t base, int rowbase, int ks,
                                          int lane, int stride) {
    return base + (uint32_t)(rowbase + (lane & 15)) * stride
         + ks * 32 + (lane >> 4) * 16;
}
// trans B-operand address: source row-major [k(s)][n(h)]; gives fragments
// identical to non-trans load of [n][k]. regs: [n0k0, n0k1, n1k0, n1k1]
__device__ __forceinline__ uint32_t taddr(uint32_t base, int colbase, int ks,
                                          int lane, int stride) {
    int s = ks * 16 + ((lane >> 3) & 1) * 8 + (lane & 7);
    int h = colbase + ((lane >> 4) & 1) * 8;
    return base + (uint32_t)s * stride + h * 2;
}

// ---------------------------------------------------------------------------
// Prep: stacked transposed weights Wt[192][384] -> fp16, padded chunk images.
// ---------------------------------------------------------------------------
__global__ void prep_kernel(const float* __restrict__ Wq,
                            const float* __restrict__ Wk,
                            const float* __restrict__ Wv) {
    int idx = blockIdx.x * 256 + threadIdx.x;
    if (idx >= 192 * 384) return;
    int n = idx / 384, c = idx % 384;
    float w;
    if (n < 64)       w = Wq[c * 64 + n];
    else if (n < 128) w = Wk[c * 64 + (n - 64)];
    else              w = Wv[c * 64 + (n - 128)];
    int chunk = c >> 6, j = c & 63;
    uint32_t off = (uint32_t)chunk * 27648u + (uint32_t)n * WSTR + j * 2;
    *(unsigned short*)(g_wh + off) = h16(w);
}

// ---------------------------------------------------------------------------
__global__ void __launch_bounds__(512, 1)
attn_kernel(const float* __restrict__ x, float* __restrict__ out) {
    extern __shared__ __align__(16) char sm[];
    const uint32_t smb = smem_u32(sm);
    const int tid  = threadIdx.x;
    const int lane = tid & 31;
    const int w    = tid >> 5;
    const int wm   = w >> 2;      // 0..3
    const int wn   = w & 3;       // 0..3
    const int b    = blockIdx.x;

    // ================= phase 1: [Q|K|V] = x @ Wt^T ==================
    float acc[2][6][4];
#pragma unroll
    for (int i = 0; i < 2; i++)
#pragma unroll
        for (int j = 0; j < 6; j++)
#pragma unroll
            for (int k = 0; k < 4; k++) acc[i][j][k] = 0.f;

    const float* xb = x + (size_t)b * (T_DIM * 384);
    {
        const char* gs = (const char*)g_wh;
        for (int i = tid; i < 1728; i += 512)
            cp16(smb + WB0_OFF + i * 16, gs + i * 16);
        CP_COMMIT();
    }
    float4 xv[4];
#pragma unroll
    for (int it = 0; it < 4; it++) {
        int i = tid + it * 512;
        xv[it] = ((const float4*)xb)[(i >> 4) * 96 + (i & 15)];
    }

    for (int chunk = 0; chunk < 6; chunk++) {
        if (chunk) __syncthreads();
        // x chunk regs -> hi/lo fp16 smem
#pragma unroll
        for (int it = 0; it < 4; it++) {
            int i = tid + it * 512;
            int t = i >> 4, f4 = i & 15;
            float4 v = xv[it];
            unsigned short h0, h1, h2, h3, l0, l1, l2, l3;
            split2h(v.x, h0, l0); split2h(v.y, h1, l1);
            split2h(v.z, h2, l2); split2h(v.w, h3, l3);
            uint32_t off = (uint32_t)t * XSTR + f4 * 8;
            *(uint2*)(sm + XH_OFF + off) = make_uint2(pack2(h0, h1), pack2(h2, h3));
            *(uint2*)(sm + XL_OFF + off) = make_uint2(pack2(l0, l1), pack2(l2, l3));
        }
        if (chunk < 5) {
            const char* gs = (const char*)(g_wh + (chunk + 1) * 27648);
            uint32_t dst = smb + (((chunk + 1) & 1) ? WB1_OFF : WB0_OFF);
            for (int i = tid; i < 1728; i += 512)
                cp16(dst + i * 16, gs + i * 16);
            CP_COMMIT();
            CP_WAIT1();
        } else {
            CP_WAIT0();
        }
        __syncthreads();
        if (chunk < 5) {
            const float4* xs = (const float4*)(xb + (chunk + 1) * 64);
#pragma unroll
            for (int it = 0; it < 4; it++) {
                int i = tid + it * 512;
                xv[it] = xs[(i >> 4) * 96 + (i & 15)];
            }
        }

        const uint32_t wbase = smb + ((chunk & 1) ? WB1_OFF : WB0_OFF);
#pragma unroll
        for (int ks = 0; ks < 4; ks++) {
            uint32_t ah[2][4], al[2][4];
#pragma unroll
            for (int mt = 0; mt < 2; mt++) {
                ldmx4(ah[mt], aaddr(smb + XH_OFF, wm * 32 + mt * 16, ks, lane, XSTR));
                ldmx4(al[mt], aaddr(smb + XL_OFF, wm * 32 + mt * 16, ks, lane, XSTR));
            }
#pragma unroll
            for (int np = 0; np < 3; np++) {
                uint32_t bh[4];
                ldmx4(bh, baddr(wbase, wn * 48 + np * 16, ks, lane, WSTR));
#pragma unroll
                for (int half = 0; half < 2; half++) {
                    int nt = np * 2 + half;
#pragma unroll
                    for (int mt = 0; mt < 2; mt++) {
                        mma16816(acc[mt][nt], ah[mt], bh + half * 2);
                        mma16816(acc[mt][nt], al[mt], bh + half * 2);
                    }
                }
            }
        }
    }
    __syncthreads();

    // write Q (x0.125, hi/lo) / K (single fp16) / V row-major (single fp16)
    const int rb0 = wm * 32 + (lane >> 2);
#pragma unroll
    for (int mt = 0; mt < 2; mt++) {
        int r = rb0 + mt * 16;
#pragma unroll
        for (int nt = 0; nt < 6; nt++) {
            int g = wn * 48 + nt * 8 + 2 * (lane & 3);
            if (g < 64) {             // Q hi/lo, pre-scaled
                unsigned short h0, l0, h1, l1, h2, l2, h3, l3;
                split2h(acc[mt][nt][0] * 0.125f, h0, l0);
                split2h(acc[mt][nt][1] * 0.125f, h1, l1);
                split2h(acc[mt][nt][2] * 0.125f, h2, l2);
                split2h(acc[mt][nt][3] * 0.125f, h3, l3);
                *(uint32_t*)(sm + QH_OFF + (uint32_t)r * QSTR + g * 2)       = pack2(h0, h1);
                *(uint32_t*)(sm + QL_OFF + (uint32_t)r * QSTR + g * 2)       = pack2(l0, l1);
                *(uint32_t*)(sm + QH_OFF + (uint32_t)(r + 8) * QSTR + g * 2) = pack2(h2, h3);
                *(uint32_t*)(sm + QL_OFF + (uint32_t)(r + 8) * QSTR + g * 2) = pack2(l2, l3);
            } else if (g < 128) {     // K single fp16
                int gc = g - 64;
                *(uint32_t*)(sm + KH_OFF + (uint32_t)r * QSTR + gc * 2) =
                    pack2(h16(acc[mt][nt][0]), h16(acc[mt][nt][1]));
                *(uint32_t*)(sm + KH_OFF + (uint32_t)(r + 8) * QSTR + gc * 2) =
                    pack2(h16(acc[mt][nt][2]), h16(acc[mt][nt][3]));
            } else {                  // V row-major [s][h]
                int hc = g - 128;
                *(uint32_t*)(sm + V_OFF + (uint32_t)r * QSTR + hc * 2) =
                    pack2(h16(acc[mt][nt][0]), h16(acc[mt][nt][1]));
                *(uint32_t*)(sm + V_OFF + (uint32_t)(r + 8) * QSTR + hc * 2) =
                    pack2(h16(acc[mt][nt][2]), h16(acc[mt][nt][3]));
            }
        }
    }
    __syncthreads();

    // ====== S = Q K^T, balanced: warp wm owns row blocks {wm, 7-wm} ======
    const int base0 = wm * 16;          // mt0 rows
    const int base1 = 112 - wm * 16;    // mt1 rows
    const int rowmax0 = base0 + 15;
    const int rowmax1 = base1 + 15;
    float sacc[2][4][4];
#pragma unroll
    for (int i = 0; i < 2; i++)
#pragma unroll
        for (int j = 0; j < 4; j++)
#pragma unroll
            for (int k = 0; k < 4; k++) sacc[i][j][k] = 0.f;

    {
        const bool any0 = (wn * 16 <= rowmax0);   // mt0 has any active column group
#pragma unroll
        for (int ks = 0; ks < 4; ks++) {
            uint32_t qh[2][4], ql[2][4];
            if (any0) {
                ldmx4(qh[0], aaddr(smb + QH_OFF, base0, ks, lane, QSTR));
                ldmx4(ql[0], aaddr(smb + QL_OFF, base0, ks, lane, QSTR));
            }
            ldmx4(qh[1], aaddr(smb + QH_OFF, base1, ks, lane, QSTR));
            ldmx4(ql[1], aaddr(smb + QL_OFF, base1, ks, lane, QSTR));
#pragma unroll
            for (int np = 0; np < 2; np++) {
                int colbase = np * 64 + wn * 16;
                if (colbase <= rowmax1) {
                    uint32_t kh[4];
                    ldmx4(kh, baddr(smb + KH_OFF, colbase, ks, lane, QSTR));
#pragma unroll
                    for (int half = 0; half < 2; half++) {
                        int nt = np * 2 + half;
                        if (colbase <= rowmax0) {
                            mma16816(sacc[0][nt], qh[0], kh + half * 2);
                            mma16816(sacc[0][nt], ql[0], kh + half * 2);
                        }
                        mma16816(sacc[1][nt], qh[1], kh + half * 2);
                        mma16816(sacc[1][nt], ql[1], kh + half * 2);
                    }
                }
            }
        }
    }

    // ---- softmax on fragments: mask, local (max,sum), merge via smem ----
    float mloc[4];
#pragma unroll
    for (int ri = 0; ri < 4; ri++) {
        int mt = ri >> 1, hb = ri & 1;
        int r = (mt ? base1 : base0) + (lane >> 2) + hb * 8;
        float m = -1e30f;
#pragma unroll
        for (int nt = 0; nt < 4; nt++) {
            int c = (nt >> 1) * 64 + wn * 16 + (nt & 1) * 8 + 2 * (lane & 3);
#pragma unroll
            for (int vv = 0; vv < 2; vv++) {
                float val = (c + vv <= r) ? sacc[mt][nt][hb * 2 + vv] : -1e30f;
                sacc[mt][nt][hb * 2 + vv] = val;
                m = fmaxf(m, val);
            }
        }
        m = fmaxf(m, __shfl_xor_sync(0xFFFFFFFFu, m, 1));
        m = fmaxf(m, __shfl_xor_sync(0xFFFFFFFFu, m, 2));
        float s = 0.f;
#pragma unroll
        for (int nt = 0; nt < 4; nt++)
#pragma unroll
            for (int vv = 0; vv < 2; vv++) {
                float e = __expf(sacc[mt][nt][hb * 2 + vv] - m);
                sacc[mt][nt][hb * 2 + vv] = e;
                s += e;
            }
        s += __shfl_xor_sync(0xFFFFFFFFu, s, 1);
        s += __shfl_xor_sync(0xFFFFFFFFu, s, 2);
        mloc[ri] = m;
        if ((lane & 3) == 0)
            *(float2*)(sm + PART_OFF + ((uint32_t)r * 4 + wn) * 8) = make_float2(m, s);
    }
    __syncthreads();

    // merge partials, write P (single fp16) — overlays dead Q region
#pragma unroll
    for (int ri = 0; ri < 4; ri++) {
        int mt = ri >> 1, hb = ri & 1;
        int r = (mt ? base1 : base0) + (lane >> 2) + hb * 8;
        const float2* pp = (const float2*)(sm + PART_OFF + (uint32_t)r * 32);
        float2 p0 = pp[0], p1 = pp[1], p2 = pp[2], p3 = pp[3];
        float mg = fmaxf(fmaxf(p0.x, p1.x), fmaxf(p2.x, p3.x));
        float sg = p0.y * __expf(p0.x - mg) + p1.y * __expf(p1.x - mg)
                 + p2.y * __expf(p2.x - mg) + p3.y * __expf(p3.x - mg);
        float fac = __expf(mloc[ri] - mg) / sg;
#pragma unroll
        for (int nt = 0; nt < 4; nt++) {
            int c = (nt >> 1) * 64 + wn * 16 + (nt & 1) * 8 + 2 * (lane & 3);
            *(uint32_t*)(sm + PH_OFF + (uint32_t)r * PSTR + c * 2) =
                pack2(h16(sacc[mt][nt][hb * 2] * fac),
                      h16(sacc[mt][nt][hb * 2 + 1] * fac));
        }
    }
    __syncthreads();

    // ===== O = P V (balanced rows; V via ldmatrix.trans; 1-MMA) =====
    {
        float oacc[2][2][4];
#pragma unroll
        for (int i = 0; i < 2; i++)
#pragma unroll
            for (int j = 0; j < 2; j++)
#pragma unroll
                for (int k = 0; k < 4; k++) oacc[i][j][k] = 0.f;

#pragma unroll
        for (int ks = 0; ks < 8; ks++) {
            bool a0 = (ks <= wm);
            bool a1 = (ks <= 7 - wm);
            if (a0 || a1) {
                uint32_t ph[2][4];
                if (a0) ldmx4(ph[0], aaddr(smb + PH_OFF, base0, ks, lane, PSTR));
                if (a1) ldmx4(ph[1], aaddr(smb + PH_OFF, base1, ks, lane, PSTR));
                uint32_t vh[4];
                ldmx4t(vh, taddr(smb + V_OFF, wn * 16, ks, lane, QSTR));
#pragma unroll
                for (int half = 0; half < 2; half++) {
                    if (a0) mma16816(oacc[0][half], ph[0], vh + half * 2);
                    if (a1) mma16816(oacc[1][half], ph[1], vh + half * 2);
                }
            }
        }
        // epilogue: fragments -> gmem
#pragma unroll
        for (int mt = 0; mt < 2; mt++) {
            int r = (mt ? base1 : base0) + (lane >> 2);
#pragma unroll
            for (int nt = 0; nt < 2; nt++) {
                int c = wn * 16 + nt * 8 + 2 * (lane & 3);
                size_t o = ((size_t)b * T_DIM + r) * H_DIM + c;
                *(float2*)(out + o)             = make_float2(oacc[mt][nt][0], oacc[mt][nt][1]);
                *(float2*)(out + o + 8 * H_DIM) = make_float2(oacc[mt][nt][2], oacc[mt][nt][3]);
            }
        }
    }
}

// ---------------------------------------------------------------------------
extern "C" void kernel_launch(void* const* d_in, const int* in_sizes, int n_in,
                              void* d_out, int out_size) {
    const float* x  = (const float*)d_in[0];
    const float* Wq = (const float*)d_in[1];
    const float* Wk = (const float*)d_in[2];
    const float* Wv = (const float*)d_in[3];
    float* out = (float*)d_out;

    cudaFuncSetAttribute(attn_kernel,
                         cudaFuncAttributeMaxDynamicSharedMemorySize, SMEM_TOTAL);

    prep_kernel<<<(192 * 384 + 255) / 256, 256>>>(Wq, Wk, Wv);
    attn_kernel<<<1024, 512, SMEM_TOTAL>>>(x, out);
}